// round 8
// baseline (speedup 1.0000x reference)
#include <cuda_runtime.h>
#include <cuda_bf16.h>
#include <math.h>
#include <stdint.h>

#define BATCH 2
#define SEQ   2048
#define DMODEL 1024
#define NHEAD 16
#define DHEAD 64
#define MTOT  (BATCH*SEQ)          // 4096
#define N_QKV (3*DMODEL)           // 3072

// ---------------------------------------------------------------------------
// Scratch (__device__ globals)
// ---------------------------------------------------------------------------
#define HTOT (BATCH*NHEAD)         // 32
__device__ __nv_bfloat16 g_xh[(size_t)MTOT * DMODEL];
__device__ __nv_bfloat16 g_xl[(size_t)MTOT * DMODEL];
__device__ __nv_bfloat16 g_wqkvT_h[(size_t)N_QKV * DMODEL];
__device__ __nv_bfloat16 g_wqkvT_l[(size_t)N_QKV * DMODEL];
__device__ __nv_bfloat16 g_woutT_h[(size_t)DMODEL * DMODEL];
__device__ __nv_bfloat16 g_woutT_l[(size_t)DMODEL * DMODEL];
// head-major [b,h,s,d] bf16 hi/lo
__device__ __nv_bfloat16 g_qh[(size_t)HTOT * SEQ * DHEAD];
__device__ __nv_bfloat16 g_ql[(size_t)HTOT * SEQ * DHEAD];
__device__ __nv_bfloat16 g_kh[(size_t)HTOT * SEQ * DHEAD];
__device__ __nv_bfloat16 g_kl[(size_t)HTOT * SEQ * DHEAD];
__device__ __nv_bfloat16 g_vh[(size_t)HTOT * SEQ * DHEAD];
__device__ __nv_bfloat16 g_vl[(size_t)HTOT * SEQ * DHEAD];
// ctx [b,s,(h,d)] hi/lo
__device__ __nv_bfloat16 g_ctxh[(size_t)MTOT * DMODEL];
__device__ __nv_bfloat16 g_ctxl[(size_t)MTOT * DMODEL];

// ---------------------------------------------------------------------------
// Helpers
// ---------------------------------------------------------------------------
__device__ __forceinline__ uint32_t smem_to_u32(const void* p) {
    uint32_t a;
    asm("{ .reg .u64 t; cvta.to.shared.u64 t, %1; cvt.u32.u64 %0, t; }" : "=r"(a) : "l"(p));
    return a;
}
__device__ __forceinline__ void ldsm_x4(uint32_t& r0, uint32_t& r1, uint32_t& r2,
                                        uint32_t& r3, uint32_t addr) {
    asm volatile("ldmatrix.sync.aligned.m8n8.x4.shared.b16 {%0,%1,%2,%3}, [%4];"
                 : "=r"(r0), "=r"(r1), "=r"(r2), "=r"(r3) : "r"(addr));
}
__device__ __forceinline__ void ldsm_x4t(uint32_t& r0, uint32_t& r1, uint32_t& r2,
                                         uint32_t& r3, uint32_t addr) {
    asm volatile("ldmatrix.sync.aligned.m8n8.x4.trans.shared.b16 {%0,%1,%2,%3}, [%4];"
                 : "=r"(r0), "=r"(r1), "=r"(r2), "=r"(r3) : "r"(addr));
}
__device__ __forceinline__ void mma_bf16(float* c, const uint32_t* a, const uint32_t* b) {
    asm volatile(
        "mma.sync.aligned.m16n8k16.row.col.f32.bf16.bf16.f32 "
        "{%0,%1,%2,%3}, {%4,%5,%6,%7}, {%8,%9}, {%0,%1,%2,%3};"
        : "+f"(c[0]), "+f"(c[1]), "+f"(c[2]), "+f"(c[3])
        : "r"(a[0]), "r"(a[1]), "r"(a[2]), "r"(a[3]), "r"(b[0]), "r"(b[1]));
}
__device__ __forceinline__ void cp_async16(uint32_t saddr, const void* gaddr) {
    asm volatile("cp.async.cg.shared.global [%0], [%1], 16;" :: "r"(saddr), "l"(gaddr));
}
#define CP_COMMIT() asm volatile("cp.async.commit_group;" ::: "memory")
#define CP_WAIT0()  asm volatile("cp.async.wait_group 0;" ::: "memory")

// pack two fp32 -> bf16x2 hi + residual bf16x2 lo
__device__ __forceinline__ void pack_split(float x, float y, uint32_t& hi, uint32_t& lo) {
    uint32_t h;
    asm("cvt.rn.bf16x2.f32 %0, %1, %2;" : "=r"(h) : "f"(y), "f"(x));
    float rx = x - __uint_as_float(h << 16);
    float ry = y - __uint_as_float(h & 0xffff0000u);
    uint32_t l;
    asm("cvt.rn.bf16x2.f32 %0, %1, %2;" : "=r"(l) : "f"(ry), "f"(rx));
    hi = h; lo = l;
}

// ---------------------------------------------------------------------------
// fp32 -> (hi, lo) bf16 split (for x)
// ---------------------------------------------------------------------------
__global__ void convert_split_kernel(const float* __restrict__ in,
                                     __nv_bfloat16* __restrict__ oh,
                                     __nv_bfloat16* __restrict__ ol, int n4)
{
    for (int i = blockIdx.x * blockDim.x + threadIdx.x; i < n4; i += gridDim.x * blockDim.x) {
        float4 v = *(const float4*)(in + (size_t)i * 4);
        uint32_t h0, l0, h1, l1;
        pack_split(v.x, v.y, h0, l0);
        pack_split(v.z, v.w, h1, l1);
        uint32_t* ph = (uint32_t*)(oh + (size_t)i * 4);
        uint32_t* pl = (uint32_t*)(ol + (size_t)i * 4);
        ph[0] = h0; ph[1] = h1;
        pl[0] = l0; pl[1] = l1;
    }
}

// ---------------------------------------------------------------------------
// w[K][N] fp32 -> wT hi/lo [N][K] bf16
// ---------------------------------------------------------------------------
__global__ void transpose_split_kernel(const float* __restrict__ w,
                                       __nv_bfloat16* __restrict__ th,
                                       __nv_bfloat16* __restrict__ tl,
                                       int K, int N)
{
    __shared__ float tile[32][33];
    const int tx = threadIdx.x, ty = threadIdx.y;
    const int x0 = blockIdx.x * 32;
    const int y0 = blockIdx.y * 32;
    #pragma unroll
    for (int i = 0; i < 4; i++) {
        int kl = ty + i * 8;
        tile[kl][tx] = w[(size_t)(y0 + kl) * N + x0 + tx];
    }
    __syncthreads();
    #pragma unroll
    for (int i = 0; i < 4; i++) {
        int nl = ty + i * 8;
        float v = tile[tx][nl];
        __nv_bfloat16 h = __float2bfloat16_rn(v);
        __nv_bfloat16 l = __float2bfloat16_rn(v - __bfloat162float(h));
        th[(size_t)(x0 + nl) * K + y0 + tx] = h;
        tl[(size_t)(x0 + nl) * K + y0 + tx] = l;
    }
}

// ---------------------------------------------------------------------------
// bf16-split tensor GEMM (mma.sync), CTA 128x128 BK32, 8 warps.
// Single-sync pipelined mainloop: wait0 -> sync -> issue(t+1) -> compute.
// ---------------------------------------------------------------------------
#define TILE_B   (128 * 80)
#define STAGE_B  (4 * TILE_B)

template<bool QKV_EPI>
__global__ __launch_bounds__(256)
void gemm_mma_kernel(const __nv_bfloat16* __restrict__ Ah, const __nv_bfloat16* __restrict__ Al,
                     const __nv_bfloat16* __restrict__ Bh, const __nv_bfloat16* __restrict__ Bl,
                     const float* __restrict__ bias, float* __restrict__ C,
                     __nv_bfloat16* __restrict__ qh, __nv_bfloat16* __restrict__ ql,
                     __nv_bfloat16* __restrict__ kh, __nv_bfloat16* __restrict__ kl,
                     __nv_bfloat16* __restrict__ vh, __nv_bfloat16* __restrict__ vl,
                     int M, int N, int K)
{
    extern __shared__ __align__(16) char smem[];
    const uint32_t sbase = smem_to_u32(smem);

    const int tid = threadIdx.x;
    const int lane = tid & 31;
    const int wid = tid >> 5;
    const int warp_m = wid >> 2;
    const int warp_n = wid & 3;
    const int bM = blockIdx.y * 128, bN = blockIdx.x * 128;

    const int grow = tid >> 2;
    const int gslot = tid & 3;
    const int NT = K / 32;

    auto issue = [&](int t) {
        const uint32_t sb = sbase + (t & 1) * STAGE_B;
        const int kof = t * 32 + gslot * 8;
        #pragma unroll
        for (int p = 0; p < 2; p++) {
            const int r = grow + p * 64;
            const uint32_t so = (uint32_t)(r * 80 + gslot * 16);
            cp_async16(sb + so,              Ah + (size_t)(bM + r) * K + kof);
            cp_async16(sb + TILE_B + so,     Al + (size_t)(bM + r) * K + kof);
            cp_async16(sb + 2 * TILE_B + so, Bh + (size_t)(bN + r) * K + kof);
            cp_async16(sb + 3 * TILE_B + so, Bl + (size_t)(bN + r) * K + kof);
        }
        CP_COMMIT();
    };

    float acc[4][4][4];
    #pragma unroll
    for (int i = 0; i < 4; i++)
        #pragma unroll
        for (int j = 0; j < 4; j++)
            #pragma unroll
            for (int k = 0; k < 4; k++) acc[i][j][k] = 0.f;

    issue(0);

    const int a_row = (lane & 7) + ((lane >> 3) & 1) * 8;
    const int a_sel = (lane >> 4);
    const int b_row = (lane & 7) + ((lane >> 4) << 3);
    const int b_sel = (lane >> 3) & 1;

    for (int t = 0; t < NT; t++) {
        CP_WAIT0();
        __syncthreads();
        if (t + 1 < NT) issue(t + 1);   // overlaps compute below; buffer safe past sync

        const uint32_t sb  = sbase + (t & 1) * STAGE_B;
        const uint32_t sAh = sb, sAl = sb + TILE_B, sBh = sb + 2 * TILE_B, sBl = sb + 3 * TILE_B;

        #pragma unroll
        for (int kk = 0; kk < 2; kk++) {
            uint32_t bh[8], bl[8];
            {
                const uint32_t ba = (uint32_t)((warp_n * 32 + b_row) * 80 + kk * 32 + b_sel * 16);
                ldsm_x4(bh[0], bh[1], bh[2], bh[3], sBh + ba);
                ldsm_x4(bh[4], bh[5], bh[6], bh[7], sBh + ba + 16 * 80);
                ldsm_x4(bl[0], bl[1], bl[2], bl[3], sBl + ba);
                ldsm_x4(bl[4], bl[5], bl[6], bl[7], sBl + ba + 16 * 80);
            }
            #pragma unroll
            for (int mt = 0; mt < 4; mt++) {
                const uint32_t aa = (uint32_t)((warp_m * 64 + mt * 16 + a_row) * 80
                                               + kk * 32 + a_sel * 16);
                uint32_t ah[4], al[4];
                ldsm_x4(ah[0], ah[1], ah[2], ah[3], sAh + aa);
                ldsm_x4(al[0], al[1], al[2], al[3], sAl + aa);
                #pragma unroll
                for (int nt = 0; nt < 4; nt++) {
                    mma_bf16(acc[mt][nt], ah, &bh[nt * 2]);
                    mma_bf16(acc[mt][nt], ah, &bl[nt * 2]);
                    mma_bf16(acc[mt][nt], al, &bh[nt * 2]);
                }
            }
        }
    }

    if (QKV_EPI) {
        const int tensor = bN >> 10;
        __nv_bfloat16* dh = (tensor == 0) ? qh : (tensor == 1) ? kh : vh;
        __nv_bfloat16* dl = (tensor == 0) ? ql : (tensor == 1) ? kl : vl;
        const float qscale = (tensor == 0) ? 0.125f : 1.0f;
        const int bb = bM >> 11;
        #pragma unroll
        for (int mt = 0; mt < 4; mt++) {
            const int srow = (bM & 2047) + warp_m * 64 + mt * 16 + (lane >> 2);
            #pragma unroll
            for (int nt = 0; nt < 4; nt++) {
                const int cg = bN + warp_n * 32 + nt * 8 + (lane & 3) * 2;
                const int hh = (cg & 1023) >> 6;
                const int d  = cg & 63;
                const size_t base = ((size_t)(bb * NHEAD + hh) * SEQ) * DHEAD + d;
                float v0 = (acc[mt][nt][0] + bias[cg])     * qscale;
                float v1 = (acc[mt][nt][1] + bias[cg + 1]) * qscale;
                float v2 = (acc[mt][nt][2] + bias[cg])     * qscale;
                float v3 = (acc[mt][nt][3] + bias[cg + 1]) * qscale;
                uint32_t h0, l0, h1, l1;
                pack_split(v0, v1, h0, l0);
                pack_split(v2, v3, h1, l1);
                *(uint32_t*)(dh + base + (size_t)srow * DHEAD)       = h0;
                *(uint32_t*)(dl + base + (size_t)srow * DHEAD)       = l0;
                *(uint32_t*)(dh + base + (size_t)(srow + 8) * DHEAD) = h1;
                *(uint32_t*)(dl + base + (size_t)(srow + 8) * DHEAD) = l1;
            }
        }
    } else {
        #pragma unroll
        for (int mt = 0; mt < 4; mt++) {
            const int r0 = bM + warp_m * 64 + mt * 16 + (lane >> 2);
            #pragma unroll
            for (int nt = 0; nt < 4; nt++) {
                const int c = bN + warp_n * 32 + nt * 8 + (lane & 3) * 2;
                const float bx = bias[c], by = bias[c + 1];
                *(float2*)(C + (size_t)r0 * N + c) =
                    make_float2(acc[mt][nt][0] + bx, acc[mt][nt][1] + by);
                *(float2*)(C + (size_t)(r0 + 8) * N + c) =
                    make_float2(acc[mt][nt][2] + bx, acc[mt][nt][3] + by);
            }
        }
    }
}

// ---------------------------------------------------------------------------
// Tensor-core flash attention, single-sync pipelined KV loop, Q frags hoisted.
// ---------------------------------------------------------------------------
#define FS_TILE 18432            // 128 rows * 144B

__global__ __launch_bounds__(256, 1)
void flash_mma_kernel(const __nv_bfloat16* __restrict__ qh, const __nv_bfloat16* __restrict__ ql,
                      const __nv_bfloat16* __restrict__ kh, const __nv_bfloat16* __restrict__ kl,
                      const __nv_bfloat16* __restrict__ vh, const __nv_bfloat16* __restrict__ vl,
                      __nv_bfloat16* __restrict__ ctxh, __nv_bfloat16* __restrict__ ctxl)
{
    extern __shared__ __align__(16) char smem[];
    const uint32_t sb = smem_to_u32(smem);
    const uint32_t QH = sb, QL = sb + FS_TILE;
    const int tid = threadIdx.x;
    const int lane = tid & 31;
    const int wid = tid >> 5;
    const int mrow = wid * 16;

    const int qt = blockIdx.x;
    const int bh = blockIdx.z * NHEAD + blockIdx.y;
    const int q0 = qt * 128;

    const size_t headbase = (size_t)bh * SEQ * DHEAD;

    const int gr = tid >> 1;
    const int gc = (tid & 1) * 4;
    const uint32_t gso = (uint32_t)(gr * 144 + gc * 16);

    // Q load
    {
        const __nv_bfloat16* pqh = qh + headbase + (size_t)(q0 + gr) * DHEAD + gc * 8;
        const __nv_bfloat16* pql = ql + headbase + (size_t)(q0 + gr) * DHEAD + gc * 8;
        #pragma unroll
        for (int c = 0; c < 4; c++) {
            cp_async16(QH + gso + c * 16, pqh + c * 8);
            cp_async16(QL + gso + c * 16, pql + c * 8);
        }
        CP_COMMIT();
    }

    auto loadKV = [&](int t) {
        const uint32_t bk = sb + 2 * FS_TILE + (t & 1) * 2 * FS_TILE;
        const uint32_t bv = sb + 6 * FS_TILE + (t & 1) * 2 * FS_TILE;
        const size_t g = headbase + (size_t)(t * 128 + gr) * DHEAD + gc * 8;
        #pragma unroll
        for (int c = 0; c < 4; c++) {
            cp_async16(bk + gso + c * 16,           kh + g + c * 8);
            cp_async16(bk + FS_TILE + gso + c * 16, kl + g + c * 8);
            cp_async16(bv + gso + c * 16,           vh + g + c * 8);
            cp_async16(bv + FS_TILE + gso + c * 16, vl + g + c * 8);
        }
        CP_COMMIT();
    };
    loadKV(0);

    const int arow = (lane & 7) + ((lane >> 3) & 1) * 8;
    const int asel = (lane >> 4);
    const int brow = (lane & 7) + ((lane >> 4) << 3);
    const int bsel = (lane >> 3) & 1;
    const uint32_t a_off = (uint32_t)((mrow + arow) * 144 + asel * 16);
    const uint32_t b_off = (uint32_t)(brow * 144 + bsel * 16);
    const uint32_t v_off = (uint32_t)(arow * 144 + asel * 16);

    uint32_t qfh[4][4], qfl[4][4];   // Q fragments, tile-invariant

    float m0 = -INFINITY, m1 = -INFINITY, l0 = 0.f, l1 = 0.f;
    float oacc[8][4];
    #pragma unroll
    for (int i = 0; i < 8; i++)
        #pragma unroll
        for (int j = 0; j < 4; j++) oacc[i][j] = 0.f;

    const int NTK = SEQ / 128;
    for (int t = 0; t < NTK; t++) {
        CP_WAIT0();
        __syncthreads();
        if (t + 1 < NTK) loadKV(t + 1);   // overlaps compute; buffer safe past sync

        if (t == 0) {
            #pragma unroll
            for (int ks = 0; ks < 4; ks++) {
                ldsm_x4(qfh[ks][0], qfh[ks][1], qfh[ks][2], qfh[ks][3], QH + a_off + ks * 32);
                ldsm_x4(qfl[ks][0], qfl[ks][1], qfl[ks][2], qfl[ks][3], QL + a_off + ks * 32);
            }
        }

        const uint32_t KHB = sb + 2 * FS_TILE + (t & 1) * 2 * FS_TILE;
        const uint32_t KLB = KHB + FS_TILE;
        const uint32_t VHB = sb + 6 * FS_TILE + (t & 1) * 2 * FS_TILE;
        const uint32_t VLB = VHB + FS_TILE;

        // ---- S = Q K^T ----
        float sacc[16][4];
        #pragma unroll
        for (int i = 0; i < 16; i++)
            #pragma unroll
            for (int j = 0; j < 4; j++) sacc[i][j] = 0.f;

        #pragma unroll
        for (int ks = 0; ks < 4; ks++) {
            #pragma unroll
            for (int np = 0; np < 8; np++) {
                uint32_t kbh[4], kbl[4];
                const uint32_t ko = b_off + (uint32_t)(np * 2304 + ks * 32);
                ldsm_x4(kbh[0], kbh[1], kbh[2], kbh[3], KHB + ko);
                ldsm_x4(kbl[0], kbl[1], kbl[2], kbl[3], KLB + ko);
                mma_bf16(sacc[np * 2],     qfh[ks], &kbh[0]);
                mma_bf16(sacc[np * 2],     qfh[ks], &kbl[0]);
                mma_bf16(sacc[np * 2],     qfl[ks], &kbh[0]);
                mma_bf16(sacc[np * 2 + 1], qfh[ks], &kbh[2]);
                mma_bf16(sacc[np * 2 + 1], qfh[ks], &kbl[2]);
                mma_bf16(sacc[np * 2 + 1], qfl[ks], &kbh[2]);
            }
        }

        // ---- online softmax ----
        float mx0 = -INFINITY, mx1 = -INFINITY;
        #pragma unroll
        for (int i = 0; i < 16; i++) {
            mx0 = fmaxf(mx0, fmaxf(sacc[i][0], sacc[i][1]));
            mx1 = fmaxf(mx1, fmaxf(sacc[i][2], sacc[i][3]));
        }
        mx0 = fmaxf(mx0, __shfl_xor_sync(0xffffffffu, mx0, 1));
        mx0 = fmaxf(mx0, __shfl_xor_sync(0xffffffffu, mx0, 2));
        mx1 = fmaxf(mx1, __shfl_xor_sync(0xffffffffu, mx1, 1));
        mx1 = fmaxf(mx1, __shfl_xor_sync(0xffffffffu, mx1, 2));
        const float mn0 = fmaxf(m0, mx0), mn1 = fmaxf(m1, mx1);
        const float c0 = __expf(m0 - mn0), c1 = __expf(m1 - mn1);
        m0 = mn0; m1 = mn1;

        float ps0 = 0.f, ps1 = 0.f;
        #pragma unroll
        for (int i = 0; i < 16; i++) {
            sacc[i][0] = __expf(sacc[i][0] - mn0); ps0 += sacc[i][0];
            sacc[i][1] = __expf(sacc[i][1] - mn0); ps0 += sacc[i][1];
            sacc[i][2] = __expf(sacc[i][2] - mn1); ps1 += sacc[i][2];
            sacc[i][3] = __expf(sacc[i][3] - mn1); ps1 += sacc[i][3];
        }
        ps0 += __shfl_xor_sync(0xffffffffu, ps0, 1);
        ps0 += __shfl_xor_sync(0xffffffffu, ps0, 2);
        ps1 += __shfl_xor_sync(0xffffffffu, ps1, 1);
        ps1 += __shfl_xor_sync(0xffffffffu, ps1, 2);
        l0 = l0 * c0 + ps0;
        l1 = l1 * c1 + ps1;

        #pragma unroll
        for (int i = 0; i < 8; i++) {
            oacc[i][0] *= c0; oacc[i][1] *= c0;
            oacc[i][2] *= c1; oacc[i][3] *= c1;
        }

        // ---- O += P V ----
        #pragma unroll
        for (int ks = 0; ks < 8; ks++) {
            uint32_t ah[4], al[4];
            pack_split(sacc[2 * ks][0],     sacc[2 * ks][1],     ah[0], al[0]);
            pack_split(sacc[2 * ks][2],     sacc[2 * ks][3],     ah[1], al[1]);
            pack_split(sacc[2 * ks + 1][0], sacc[2 * ks + 1][1], ah[2], al[2]);
            pack_split(sacc[2 * ks + 1][2], sacc[2 * ks + 1][3], ah[3], al[3]);
            #pragma unroll
            for (int nt = 0; nt < 4; nt++) {
                uint32_t vbh[4], vbl[4];
                const uint32_t vo = v_off + (uint32_t)(ks * 2304 + nt * 32);
                ldsm_x4t(vbh[0], vbh[1], vbh[2], vbh[3], VHB + vo);
                ldsm_x4t(vbl[0], vbl[1], vbl[2], vbl[3], VLB + vo);
                mma_bf16(oacc[nt * 2],     ah, &vbh[0]);
                mma_bf16(oacc[nt * 2],     ah, &vbl[0]);
                mma_bf16(oacc[nt * 2],     al, &vbh[0]);
                mma_bf16(oacc[nt * 2 + 1], ah, &vbh[2]);
                mma_bf16(oacc[nt * 2 + 1], ah, &vbl[2]);
                mma_bf16(oacc[nt * 2 + 1], al, &vbh[2]);
            }
        }
    }

    // ---- epilogue ----
    const float inv0 = 1.f / l0, inv1 = 1.f / l1;
    const int row0 = q0 + mrow + (lane >> 2);
    const size_t base0 = ((size_t)blockIdx.z * SEQ + row0) * DMODEL
                         + blockIdx.y * DHEAD + (lane & 3) * 2;
    const size_t base1 = base0 + 8 * DMODEL;
    #pragma unroll
    for (int nt = 0; nt < 8; nt++) {
        uint32_t h, l;
        pack_split(oacc[nt][0] * inv0, oacc[nt][1] * inv0, h, l);
        *(uint32_t*)(ctxh + base0 + nt * 8) = h;
        *(uint32_t*)(ctxl + base0 + nt * 8) = l;
        pack_split(oacc[nt][2] * inv1, oacc[nt][3] * inv1, h, l);
        *(uint32_t*)(ctxh + base1 + nt * 8) = h;
        *(uint32_t*)(ctxl + base1 + nt * 8) = l;
    }
}

// ---------------------------------------------------------------------------
extern "C" void kernel_launch(void* const* d_in, const int* in_sizes, int n_in,
                              void* d_out, int out_size)
{
    const float* x      = (const float*)d_in[0];
    const float* w_qkv  = (const float*)d_in[1];
    const float* b_qkv  = (const float*)d_in[2];
    const float* w_out  = (const float*)d_in[3];
    const float* b_out  = (const float*)d_in[4];
    float* out = (float*)d_out;

    __nv_bfloat16 *xh, *xl, *wqh, *wql, *woh, *wol;
    __nv_bfloat16 *qh, *ql, *kh, *kl, *vh, *vl, *ch, *cl;
    cudaGetSymbolAddress((void**)&xh, g_xh);
    cudaGetSymbolAddress((void**)&xl, g_xl);
    cudaGetSymbolAddress((void**)&wqh, g_wqkvT_h);
    cudaGetSymbolAddress((void**)&wql, g_wqkvT_l);
    cudaGetSymbolAddress((void**)&woh, g_woutT_h);
    cudaGetSymbolAddress((void**)&wol, g_woutT_l);
    cudaGetSymbolAddress((void**)&qh, g_qh);
    cudaGetSymbolAddress((void**)&ql, g_ql);
    cudaGetSymbolAddress((void**)&kh, g_kh);
    cudaGetSymbolAddress((void**)&kl, g_kl);
    cudaGetSymbolAddress((void**)&vh, g_vh);
    cudaGetSymbolAddress((void**)&vl, g_vl);
    cudaGetSymbolAddress((void**)&ch, g_ctxh);
    cudaGetSymbolAddress((void**)&cl, g_ctxl);

    const int GEMM_SMEM  = 2 * STAGE_B;     // 81920
    const int FLASH_SMEM = 10 * FS_TILE;    // 184320
    cudaFuncSetAttribute(gemm_mma_kernel<true>,
                         cudaFuncAttributeMaxDynamicSharedMemorySize, GEMM_SMEM);
    cudaFuncSetAttribute(gemm_mma_kernel<false>,
                         cudaFuncAttributeMaxDynamicSharedMemorySize, GEMM_SMEM);
    cudaFuncSetAttribute(flash_mma_kernel,
                         cudaFuncAttributeMaxDynamicSharedMemorySize, FLASH_SMEM);

    // 0) conversions
    convert_split_kernel<<<2048, 256>>>(x, xh, xl, MTOT * DMODEL / 4);
    transpose_split_kernel<<<dim3(N_QKV / 32, DMODEL / 32), dim3(32, 8)>>>(
        w_qkv, wqh, wql, DMODEL, N_QKV);
    transpose_split_kernel<<<dim3(DMODEL / 32, DMODEL / 32), dim3(32, 8)>>>(
        w_out, woh, wol, DMODEL, DMODEL);

    // 1) QKV projection -> q/k/v head-major bf16 hi/lo (q pre-scaled)
    {
        dim3 grid(N_QKV / 128, MTOT / 128);
        gemm_mma_kernel<true><<<grid, 256, GEMM_SMEM>>>(
            xh, xl, wqh, wql, b_qkv, nullptr,
            qh, ql, kh, kl, vh, vl, MTOT, N_QKV, DMODEL);
    }
    // 2) Tensor-core flash attention -> ctx hi/lo
    {
        dim3 grid(SEQ / 128, NHEAD, BATCH);
        flash_mma_kernel<<<grid, 256, FLASH_SMEM>>>(qh, ql, kh, kl, vh, vl, ch, cl);
    }
    // 3) Output projection -> fp32 out
    {
        dim3 grid(DMODEL / 128, MTOT / 128);
        gemm_mma_kernel<false><<<grid, 256, GEMM_SMEM>>>(
            ch, cl, woh, wol, b_out, out,
            nullptr, nullptr, nullptr, nullptr, nullptr, nullptr,
            MTOT, DMODEL, DMODEL);
    }
}

// round 9
// speedup vs baseline: 1.0006x; 1.0006x over previous
#include <cuda_runtime.h>
#include <cuda_bf16.h>
#include <math.h>
#include <stdint.h>

#define BATCH 2
#define SEQ   2048
#define DMODEL 1024
#define NHEAD 16
#define DHEAD 64
#define MTOT  (BATCH*SEQ)          // 4096
#define N_QKV (3*DMODEL)           // 3072

// ---------------------------------------------------------------------------
// Scratch (__device__ globals)
// ---------------------------------------------------------------------------
#define HTOT (BATCH*NHEAD)         // 32
__device__ __nv_bfloat16 g_xh[(size_t)MTOT * DMODEL];
__device__ __nv_bfloat16 g_xl[(size_t)MTOT * DMODEL];
__device__ __nv_bfloat16 g_wqkvT_h[(size_t)N_QKV * DMODEL];
__device__ __nv_bfloat16 g_wqkvT_l[(size_t)N_QKV * DMODEL];
__device__ __nv_bfloat16 g_woutT_h[(size_t)DMODEL * DMODEL];
__device__ __nv_bfloat16 g_woutT_l[(size_t)DMODEL * DMODEL];
// head-major [b,h,s,d] bf16 hi/lo
__device__ __nv_bfloat16 g_qh[(size_t)HTOT * SEQ * DHEAD];
__device__ __nv_bfloat16 g_ql[(size_t)HTOT * SEQ * DHEAD];
__device__ __nv_bfloat16 g_kh[(size_t)HTOT * SEQ * DHEAD];
__device__ __nv_bfloat16 g_kl[(size_t)HTOT * SEQ * DHEAD];
__device__ __nv_bfloat16 g_vh[(size_t)HTOT * SEQ * DHEAD];
__device__ __nv_bfloat16 g_vl[(size_t)HTOT * SEQ * DHEAD];
// ctx [b,s,(h,d)] hi/lo
__device__ __nv_bfloat16 g_ctxh[(size_t)MTOT * DMODEL];
__device__ __nv_bfloat16 g_ctxl[(size_t)MTOT * DMODEL];

// ---------------------------------------------------------------------------
// Helpers
// ---------------------------------------------------------------------------
__device__ __forceinline__ uint32_t smem_to_u32(const void* p) {
    uint32_t a;
    asm("{ .reg .u64 t; cvta.to.shared.u64 t, %1; cvt.u32.u64 %0, t; }" : "=r"(a) : "l"(p));
    return a;
}
__device__ __forceinline__ void ldsm_x4(uint32_t& r0, uint32_t& r1, uint32_t& r2,
                                        uint32_t& r3, uint32_t addr) {
    asm volatile("ldmatrix.sync.aligned.m8n8.x4.shared.b16 {%0,%1,%2,%3}, [%4];"
                 : "=r"(r0), "=r"(r1), "=r"(r2), "=r"(r3) : "r"(addr));
}
__device__ __forceinline__ void ldsm_x4t(uint32_t& r0, uint32_t& r1, uint32_t& r2,
                                         uint32_t& r3, uint32_t addr) {
    asm volatile("ldmatrix.sync.aligned.m8n8.x4.trans.shared.b16 {%0,%1,%2,%3}, [%4];"
                 : "=r"(r0), "=r"(r1), "=r"(r2), "=r"(r3) : "r"(addr));
}
__device__ __forceinline__ void mma_bf16(float* c, const uint32_t* a, const uint32_t* b) {
    asm volatile(
        "mma.sync.aligned.m16n8k16.row.col.f32.bf16.bf16.f32 "
        "{%0,%1,%2,%3}, {%4,%5,%6,%7}, {%8,%9}, {%0,%1,%2,%3};"
        : "+f"(c[0]), "+f"(c[1]), "+f"(c[2]), "+f"(c[3])
        : "r"(a[0]), "r"(a[1]), "r"(a[2]), "r"(a[3]), "r"(b[0]), "r"(b[1]));
}
__device__ __forceinline__ void cp_async16(uint32_t saddr, const void* gaddr) {
    asm volatile("cp.async.cg.shared.global [%0], [%1], 16;" :: "r"(saddr), "l"(gaddr));
}
#define CP_COMMIT() asm volatile("cp.async.commit_group;" ::: "memory")
#define CP_WAIT0()  asm volatile("cp.async.wait_group 0;" ::: "memory")

// pack two fp32 -> bf16x2 hi + residual bf16x2 lo
__device__ __forceinline__ void pack_split(float x, float y, uint32_t& hi, uint32_t& lo) {
    uint32_t h;
    asm("cvt.rn.bf16x2.f32 %0, %1, %2;" : "=r"(h) : "f"(y), "f"(x));
    float rx = x - __uint_as_float(h << 16);
    float ry = y - __uint_as_float(h & 0xffff0000u);
    uint32_t l;
    asm("cvt.rn.bf16x2.f32 %0, %1, %2;" : "=r"(l) : "f"(ry), "f"(rx));
    hi = h; lo = l;
}

// ---------------------------------------------------------------------------
// fp32 -> (hi, lo) bf16 split (for x)
// ---------------------------------------------------------------------------
__global__ void convert_split_kernel(const float* __restrict__ in,
                                     __nv_bfloat16* __restrict__ oh,
                                     __nv_bfloat16* __restrict__ ol, int n4)
{
    for (int i = blockIdx.x * blockDim.x + threadIdx.x; i < n4; i += gridDim.x * blockDim.x) {
        float4 v = *(const float4*)(in + (size_t)i * 4);
        uint32_t h0, l0, h1, l1;
        pack_split(v.x, v.y, h0, l0);
        pack_split(v.z, v.w, h1, l1);
        uint32_t* ph = (uint32_t*)(oh + (size_t)i * 4);
        uint32_t* pl = (uint32_t*)(ol + (size_t)i * 4);
        ph[0] = h0; ph[1] = h1;
        pl[0] = l0; pl[1] = l1;
    }
}

// ---------------------------------------------------------------------------
// w[K][N] fp32 -> wT hi/lo [N][K] bf16
// ---------------------------------------------------------------------------
__global__ void transpose_split_kernel(const float* __restrict__ w,
                                       __nv_bfloat16* __restrict__ th,
                                       __nv_bfloat16* __restrict__ tl,
                                       int K, int N)
{
    __shared__ float tile[32][33];
    const int tx = threadIdx.x, ty = threadIdx.y;
    const int x0 = blockIdx.x * 32;
    const int y0 = blockIdx.y * 32;
    #pragma unroll
    for (int i = 0; i < 4; i++) {
        int kl = ty + i * 8;
        tile[kl][tx] = w[(size_t)(y0 + kl) * N + x0 + tx];
    }
    __syncthreads();
    #pragma unroll
    for (int i = 0; i < 4; i++) {
        int nl = ty + i * 8;
        float v = tile[tx][nl];
        __nv_bfloat16 h = __float2bfloat16_rn(v);
        __nv_bfloat16 l = __float2bfloat16_rn(v - __bfloat162float(h));
        th[(size_t)(x0 + nl) * K + y0 + tx] = h;
        tl[(size_t)(x0 + nl) * K + y0 + tx] = l;
    }
}

// ---------------------------------------------------------------------------
// bf16-split tensor GEMM (mma.sync), CTA 128x128 BK32, 8 warps.
// MMA schedule: split-major, nt inner -> same-acc chain distance 4.
// ---------------------------------------------------------------------------
#define TILE_B   (128 * 80)
#define STAGE_B  (4 * TILE_B)

template<bool QKV_EPI>
__global__ __launch_bounds__(256)
void gemm_mma_kernel(const __nv_bfloat16* __restrict__ Ah, const __nv_bfloat16* __restrict__ Al,
                     const __nv_bfloat16* __restrict__ Bh, const __nv_bfloat16* __restrict__ Bl,
                     const float* __restrict__ bias, float* __restrict__ C,
                     __nv_bfloat16* __restrict__ qh, __nv_bfloat16* __restrict__ ql,
                     __nv_bfloat16* __restrict__ kh, __nv_bfloat16* __restrict__ kl,
                     __nv_bfloat16* __restrict__ vh, __nv_bfloat16* __restrict__ vl,
                     int M, int N, int K)
{
    extern __shared__ __align__(16) char smem[];
    const uint32_t sbase = smem_to_u32(smem);

    const int tid = threadIdx.x;
    const int lane = tid & 31;
    const int wid = tid >> 5;
    const int warp_m = wid >> 2;
    const int warp_n = wid & 3;
    const int bM = blockIdx.y * 128, bN = blockIdx.x * 128;

    const int grow = tid >> 2;
    const int gslot = tid & 3;
    const int NT = K / 32;

    auto issue = [&](int t) {
        const uint32_t sb = sbase + (t & 1) * STAGE_B;
        const int kof = t * 32 + gslot * 8;
        #pragma unroll
        for (int p = 0; p < 2; p++) {
            const int r = grow + p * 64;
            const uint32_t so = (uint32_t)(r * 80 + gslot * 16);
            cp_async16(sb + so,              Ah + (size_t)(bM + r) * K + kof);
            cp_async16(sb + TILE_B + so,     Al + (size_t)(bM + r) * K + kof);
            cp_async16(sb + 2 * TILE_B + so, Bh + (size_t)(bN + r) * K + kof);
            cp_async16(sb + 3 * TILE_B + so, Bl + (size_t)(bN + r) * K + kof);
        }
        CP_COMMIT();
    };

    float acc[4][4][4];
    #pragma unroll
    for (int i = 0; i < 4; i++)
        #pragma unroll
        for (int j = 0; j < 4; j++)
            #pragma unroll
            for (int k = 0; k < 4; k++) acc[i][j][k] = 0.f;

    issue(0);

    const int a_row = (lane & 7) + ((lane >> 3) & 1) * 8;
    const int a_sel = (lane >> 4);
    const int b_row = (lane & 7) + ((lane >> 4) << 3);
    const int b_sel = (lane >> 3) & 1;

    for (int t = 0; t < NT; t++) {
        CP_WAIT0();
        __syncthreads();
        if (t + 1 < NT) issue(t + 1);

        const uint32_t sb  = sbase + (t & 1) * STAGE_B;
        const uint32_t sAh = sb, sAl = sb + TILE_B, sBh = sb + 2 * TILE_B, sBl = sb + 3 * TILE_B;

        #pragma unroll
        for (int kk = 0; kk < 2; kk++) {
            uint32_t bh[8], bl[8];
            {
                const uint32_t ba = (uint32_t)((warp_n * 32 + b_row) * 80 + kk * 32 + b_sel * 16);
                ldsm_x4(bh[0], bh[1], bh[2], bh[3], sBh + ba);
                ldsm_x4(bh[4], bh[5], bh[6], bh[7], sBh + ba + 16 * 80);
                ldsm_x4(bl[0], bl[1], bl[2], bl[3], sBl + ba);
                ldsm_x4(bl[4], bl[5], bl[6], bl[7], sBl + ba + 16 * 80);
            }
            #pragma unroll
            for (int mt = 0; mt < 4; mt++) {
                const uint32_t aa = (uint32_t)((warp_m * 64 + mt * 16 + a_row) * 80
                                               + kk * 32 + a_sel * 16);
                uint32_t ah[4], al[4];
                ldsm_x4(ah[0], ah[1], ah[2], ah[3], sAh + aa);
                ldsm_x4(al[0], al[1], al[2], al[3], sAl + aa);
                // split-major, nt inner: same-acc chain distance = 4
                mma_bf16(acc[mt][0], ah, &bh[0]);
                mma_bf16(acc[mt][1], ah, &bh[2]);
                mma_bf16(acc[mt][2], ah, &bh[4]);
                mma_bf16(acc[mt][3], ah, &bh[6]);
                mma_bf16(acc[mt][0], ah, &bl[0]);
                mma_bf16(acc[mt][1], ah, &bl[2]);
                mma_bf16(acc[mt][2], ah, &bl[4]);
                mma_bf16(acc[mt][3], ah, &bl[6]);
                mma_bf16(acc[mt][0], al, &bh[0]);
                mma_bf16(acc[mt][1], al, &bh[2]);
                mma_bf16(acc[mt][2], al, &bh[4]);
                mma_bf16(acc[mt][3], al, &bh[6]);
            }
        }
    }

    if (QKV_EPI) {
        const int tensor = bN >> 10;
        __nv_bfloat16* dh = (tensor == 0) ? qh : (tensor == 1) ? kh : vh;
        __nv_bfloat16* dl = (tensor == 0) ? ql : (tensor == 1) ? kl : vl;
        const float qscale = (tensor == 0) ? 0.125f : 1.0f;
        const int bb = bM >> 11;
        #pragma unroll
        for (int mt = 0; mt < 4; mt++) {
            const int srow = (bM & 2047) + warp_m * 64 + mt * 16 + (lane >> 2);
            #pragma unroll
            for (int nt = 0; nt < 4; nt++) {
                const int cg = bN + warp_n * 32 + nt * 8 + (lane & 3) * 2;
                const int hh = (cg & 1023) >> 6;
                const int d  = cg & 63;
                const size_t base = ((size_t)(bb * NHEAD + hh) * SEQ) * DHEAD + d;
                float v0 = (acc[mt][nt][0] + bias[cg])     * qscale;
                float v1 = (acc[mt][nt][1] + bias[cg + 1]) * qscale;
                float v2 = (acc[mt][nt][2] + bias[cg])     * qscale;
                float v3 = (acc[mt][nt][3] + bias[cg + 1]) * qscale;
                uint32_t h0, l0, h1, l1;
                pack_split(v0, v1, h0, l0);
                pack_split(v2, v3, h1, l1);
                *(uint32_t*)(dh + base + (size_t)srow * DHEAD)       = h0;
                *(uint32_t*)(dl + base + (size_t)srow * DHEAD)       = l0;
                *(uint32_t*)(dh + base + (size_t)(srow + 8) * DHEAD) = h1;
                *(uint32_t*)(dl + base + (size_t)(srow + 8) * DHEAD) = l1;
            }
        }
    } else {
        #pragma unroll
        for (int mt = 0; mt < 4; mt++) {
            const int r0 = bM + warp_m * 64 + mt * 16 + (lane >> 2);
            #pragma unroll
            for (int nt = 0; nt < 4; nt++) {
                const int c = bN + warp_n * 32 + nt * 8 + (lane & 3) * 2;
                const float bx = bias[c], by = bias[c + 1];
                *(float2*)(C + (size_t)r0 * N + c) =
                    make_float2(acc[mt][nt][0] + bx, acc[mt][nt][1] + by);
                *(float2*)(C + (size_t)(r0 + 8) * N + c) =
                    make_float2(acc[mt][nt][2] + bx, acc[mt][nt][3] + by);
            }
        }
    }
}

// ---------------------------------------------------------------------------
// Tensor-core flash attention; MMA schedules reordered for chain distance 4.
// ---------------------------------------------------------------------------
#define FS_TILE 18432            // 128 rows * 144B

__global__ __launch_bounds__(256, 1)
void flash_mma_kernel(const __nv_bfloat16* __restrict__ qh, const __nv_bfloat16* __restrict__ ql,
                      const __nv_bfloat16* __restrict__ kh, const __nv_bfloat16* __restrict__ kl,
                      const __nv_bfloat16* __restrict__ vh, const __nv_bfloat16* __restrict__ vl,
                      __nv_bfloat16* __restrict__ ctxh, __nv_bfloat16* __restrict__ ctxl)
{
    extern __shared__ __align__(16) char smem[];
    const uint32_t sb = smem_to_u32(smem);
    const uint32_t QH = sb, QL = sb + FS_TILE;
    const int tid = threadIdx.x;
    const int lane = tid & 31;
    const int wid = tid >> 5;
    const int mrow = wid * 16;

    const int qt = blockIdx.x;
    const int bh = blockIdx.z * NHEAD + blockIdx.y;
    const int q0 = qt * 128;

    const size_t headbase = (size_t)bh * SEQ * DHEAD;

    const int gr = tid >> 1;
    const int gc = (tid & 1) * 4;
    const uint32_t gso = (uint32_t)(gr * 144 + gc * 16);

    // Q load
    {
        const __nv_bfloat16* pqh = qh + headbase + (size_t)(q0 + gr) * DHEAD + gc * 8;
        const __nv_bfloat16* pql = ql + headbase + (size_t)(q0 + gr) * DHEAD + gc * 8;
        #pragma unroll
        for (int c = 0; c < 4; c++) {
            cp_async16(QH + gso + c * 16, pqh + c * 8);
            cp_async16(QL + gso + c * 16, pql + c * 8);
        }
        CP_COMMIT();
    }

    auto loadKV = [&](int t) {
        const uint32_t bk = sb + 2 * FS_TILE + (t & 1) * 2 * FS_TILE;
        const uint32_t bv = sb + 6 * FS_TILE + (t & 1) * 2 * FS_TILE;
        const size_t g = headbase + (size_t)(t * 128 + gr) * DHEAD + gc * 8;
        #pragma unroll
        for (int c = 0; c < 4; c++) {
            cp_async16(bk + gso + c * 16,           kh + g + c * 8);
            cp_async16(bk + FS_TILE + gso + c * 16, kl + g + c * 8);
            cp_async16(bv + gso + c * 16,           vh + g + c * 8);
            cp_async16(bv + FS_TILE + gso + c * 16, vl + g + c * 8);
        }
        CP_COMMIT();
    };
    loadKV(0);

    const int arow = (lane & 7) + ((lane >> 3) & 1) * 8;
    const int asel = (lane >> 4);
    const int brow = (lane & 7) + ((lane >> 4) << 3);
    const int bsel = (lane >> 3) & 1;
    const uint32_t a_off = (uint32_t)((mrow + arow) * 144 + asel * 16);
    const uint32_t b_off = (uint32_t)(brow * 144 + bsel * 16);
    const uint32_t v_off = (uint32_t)(arow * 144 + asel * 16);

    uint32_t qfh[4][4], qfl[4][4];

    float m0 = -INFINITY, m1 = -INFINITY, l0 = 0.f, l1 = 0.f;
    float oacc[8][4];
    #pragma unroll
    for (int i = 0; i < 8; i++)
        #pragma unroll
        for (int j = 0; j < 4; j++) oacc[i][j] = 0.f;

    const int NTK = SEQ / 128;
    for (int t = 0; t < NTK; t++) {
        CP_WAIT0();
        __syncthreads();
        if (t + 1 < NTK) loadKV(t + 1);

        if (t == 0) {
            #pragma unroll
            for (int ks = 0; ks < 4; ks++) {
                ldsm_x4(qfh[ks][0], qfh[ks][1], qfh[ks][2], qfh[ks][3], QH + a_off + ks * 32);
                ldsm_x4(qfl[ks][0], qfl[ks][1], qfl[ks][2], qfl[ks][3], QL + a_off + ks * 32);
            }
        }

        const uint32_t KHB = sb + 2 * FS_TILE + (t & 1) * 2 * FS_TILE;
        const uint32_t KLB = KHB + FS_TILE;
        const uint32_t VHB = sb + 6 * FS_TILE + (t & 1) * 2 * FS_TILE;
        const uint32_t VLB = VHB + FS_TILE;

        // ---- S = Q K^T : np processed in pairs, split-major over 4 accs ----
        float sacc[16][4];
        #pragma unroll
        for (int i = 0; i < 16; i++)
            #pragma unroll
            for (int j = 0; j < 4; j++) sacc[i][j] = 0.f;

        #pragma unroll
        for (int ks = 0; ks < 4; ks++) {
            #pragma unroll
            for (int npp = 0; npp < 4; npp++) {
                uint32_t kbh[8], kbl[8];
                const uint32_t ko = b_off + (uint32_t)(npp * 2 * 2304 + ks * 32);
                ldsm_x4(kbh[0], kbh[1], kbh[2], kbh[3], KHB + ko);
                ldsm_x4(kbh[4], kbh[5], kbh[6], kbh[7], KHB + ko + 2304);
                ldsm_x4(kbl[0], kbl[1], kbl[2], kbl[3], KLB + ko);
                ldsm_x4(kbl[4], kbl[5], kbl[6], kbl[7], KLB + ko + 2304);
                float* s0 = sacc[npp * 4 + 0];
                float* s1 = sacc[npp * 4 + 1];
                float* s2 = sacc[npp * 4 + 2];
                float* s3 = sacc[npp * 4 + 3];
                mma_bf16(s0, qfh[ks], &kbh[0]);
                mma_bf16(s1, qfh[ks], &kbh[2]);
                mma_bf16(s2, qfh[ks], &kbh[4]);
                mma_bf16(s3, qfh[ks], &kbh[6]);
                mma_bf16(s0, qfh[ks], &kbl[0]);
                mma_bf16(s1, qfh[ks], &kbl[2]);
                mma_bf16(s2, qfh[ks], &kbl[4]);
                mma_bf16(s3, qfh[ks], &kbl[6]);
                mma_bf16(s0, qfl[ks], &kbh[0]);
                mma_bf16(s1, qfl[ks], &kbh[2]);
                mma_bf16(s2, qfl[ks], &kbh[4]);
                mma_bf16(s3, qfl[ks], &kbh[6]);
            }
        }

        // ---- online softmax ----
        float mx0 = -INFINITY, mx1 = -INFINITY;
        #pragma unroll
        for (int i = 0; i < 16; i++) {
            mx0 = fmaxf(mx0, fmaxf(sacc[i][0], sacc[i][1]));
            mx1 = fmaxf(mx1, fmaxf(sacc[i][2], sacc[i][3]));
        }
        mx0 = fmaxf(mx0, __shfl_xor_sync(0xffffffffu, mx0, 1));
        mx0 = fmaxf(mx0, __shfl_xor_sync(0xffffffffu, mx0, 2));
        mx1 = fmaxf(mx1, __shfl_xor_sync(0xffffffffu, mx1, 1));
        mx1 = fmaxf(mx1, __shfl_xor_sync(0xffffffffu, mx1, 2));
        const float mn0 = fmaxf(m0, mx0), mn1 = fmaxf(m1, mx1);
        const float c0 = __expf(m0 - mn0), c1 = __expf(m1 - mn1);
        m0 = mn0; m1 = mn1;

        float ps0 = 0.f, ps1 = 0.f;
        #pragma unroll
        for (int i = 0; i < 16; i++) {
            sacc[i][0] = __expf(sacc[i][0] - mn0); ps0 += sacc[i][0];
            sacc[i][1] = __expf(sacc[i][1] - mn0); ps0 += sacc[i][1];
            sacc[i][2] = __expf(sacc[i][2] - mn1); ps1 += sacc[i][2];
            sacc[i][3] = __expf(sacc[i][3] - mn1); ps1 += sacc[i][3];
        }
        ps0 += __shfl_xor_sync(0xffffffffu, ps0, 1);
        ps0 += __shfl_xor_sync(0xffffffffu, ps0, 2);
        ps1 += __shfl_xor_sync(0xffffffffu, ps1, 1);
        ps1 += __shfl_xor_sync(0xffffffffu, ps1, 2);
        l0 = l0 * c0 + ps0;
        l1 = l1 * c1 + ps1;

        #pragma unroll
        for (int i = 0; i < 8; i++) {
            oacc[i][0] *= c0; oacc[i][1] *= c0;
            oacc[i][2] *= c1; oacc[i][3] *= c1;
        }

        // ---- O += P V : nt processed in pairs, split-major over 4 accs ----
        #pragma unroll
        for (int ks = 0; ks < 8; ks++) {
            uint32_t ah[4], al[4];
            pack_split(sacc[2 * ks][0],     sacc[2 * ks][1],     ah[0], al[0]);
            pack_split(sacc[2 * ks][2],     sacc[2 * ks][3],     ah[1], al[1]);
            pack_split(sacc[2 * ks + 1][0], sacc[2 * ks + 1][1], ah[2], al[2]);
            pack_split(sacc[2 * ks + 1][2], sacc[2 * ks + 1][3], ah[3], al[3]);
            #pragma unroll
            for (int ntp = 0; ntp < 2; ntp++) {
                uint32_t vbh[8], vbl[8];
                const uint32_t vo = v_off + (uint32_t)(ks * 2304 + ntp * 64);
                ldsm_x4t(vbh[0], vbh[1], vbh[2], vbh[3], VHB + vo);
                ldsm_x4t(vbh[4], vbh[5], vbh[6], vbh[7], VHB + vo + 32);
                ldsm_x4t(vbl[0], vbl[1], vbl[2], vbl[3], VLB + vo);
                ldsm_x4t(vbl[4], vbl[5], vbl[6], vbl[7], VLB + vo + 32);
                float* o0 = oacc[ntp * 4 + 0];
                float* o1 = oacc[ntp * 4 + 1];
                float* o2 = oacc[ntp * 4 + 2];
                float* o3 = oacc[ntp * 4 + 3];
                mma_bf16(o0, ah, &vbh[0]);
                mma_bf16(o1, ah, &vbh[2]);
                mma_bf16(o2, ah, &vbh[4]);
                mma_bf16(o3, ah, &vbh[6]);
                mma_bf16(o0, ah, &vbl[0]);
                mma_bf16(o1, ah, &vbl[2]);
                mma_bf16(o2, ah, &vbl[4]);
                mma_bf16(o3, ah, &vbl[6]);
                mma_bf16(o0, al, &vbh[0]);
                mma_bf16(o1, al, &vbh[2]);
                mma_bf16(o2, al, &vbh[4]);
                mma_bf16(o3, al, &vbh[6]);
            }
        }
    }

    // ---- epilogue ----
    const float inv0 = 1.f / l0, inv1 = 1.f / l1;
    const int row0 = q0 + mrow + (lane >> 2);
    const size_t base0 = ((size_t)blockIdx.z * SEQ + row0) * DMODEL
                         + blockIdx.y * DHEAD + (lane & 3) * 2;
    const size_t base1 = base0 + 8 * DMODEL;
    #pragma unroll
    for (int nt = 0; nt < 8; nt++) {
        uint32_t h, l;
        pack_split(oacc[nt][0] * inv0, oacc[nt][1] * inv0, h, l);
        *(uint32_t*)(ctxh + base0 + nt * 8) = h;
        *(uint32_t*)(ctxl + base0 + nt * 8) = l;
        pack_split(oacc[nt][2] * inv1, oacc[nt][3] * inv1, h, l);
        *(uint32_t*)(ctxh + base1 + nt * 8) = h;
        *(uint32_t*)(ctxl + base1 + nt * 8) = l;
    }
}

// ---------------------------------------------------------------------------
extern "C" void kernel_launch(void* const* d_in, const int* in_sizes, int n_in,
                              void* d_out, int out_size)
{
    const float* x      = (const float*)d_in[0];
    const float* w_qkv  = (const float*)d_in[1];
    const float* b_qkv  = (const float*)d_in[2];
    const float* w_out  = (const float*)d_in[3];
    const float* b_out  = (const float*)d_in[4];
    float* out = (float*)d_out;

    __nv_bfloat16 *xh, *xl, *wqh, *wql, *woh, *wol;
    __nv_bfloat16 *qh, *ql, *kh, *kl, *vh, *vl, *ch, *cl;
    cudaGetSymbolAddress((void**)&xh, g_xh);
    cudaGetSymbolAddress((void**)&xl, g_xl);
    cudaGetSymbolAddress((void**)&wqh, g_wqkvT_h);
    cudaGetSymbolAddress((void**)&wql, g_wqkvT_l);
    cudaGetSymbolAddress((void**)&woh, g_woutT_h);
    cudaGetSymbolAddress((void**)&wol, g_woutT_l);
    cudaGetSymbolAddress((void**)&qh, g_qh);
    cudaGetSymbolAddress((void**)&ql, g_ql);
    cudaGetSymbolAddress((void**)&kh, g_kh);
    cudaGetSymbolAddress((void**)&kl, g_kl);
    cudaGetSymbolAddress((void**)&vh, g_vh);
    cudaGetSymbolAddress((void**)&vl, g_vl);
    cudaGetSymbolAddress((void**)&ch, g_ctxh);
    cudaGetSymbolAddress((void**)&cl, g_ctxl);

    const int GEMM_SMEM  = 2 * STAGE_B;     // 81920
    const int FLASH_SMEM = 10 * FS_TILE;    // 184320
    cudaFuncSetAttribute(gemm_mma_kernel<true>,
                         cudaFuncAttributeMaxDynamicSharedMemorySize, GEMM_SMEM);
    cudaFuncSetAttribute(gemm_mma_kernel<false>,
                         cudaFuncAttributeMaxDynamicSharedMemorySize, GEMM_SMEM);
    cudaFuncSetAttribute(flash_mma_kernel,
                         cudaFuncAttributeMaxDynamicSharedMemorySize, FLASH_SMEM);

    // 0) conversions
    convert_split_kernel<<<2048, 256>>>(x, xh, xl, MTOT * DMODEL / 4);
    transpose_split_kernel<<<dim3(N_QKV / 32, DMODEL / 32), dim3(32, 8)>>>(
        w_qkv, wqh, wql, DMODEL, N_QKV);
    transpose_split_kernel<<<dim3(DMODEL / 32, DMODEL / 32), dim3(32, 8)>>>(
        w_out, woh, wol, DMODEL, DMODEL);

    // 1) QKV projection -> q/k/v head-major bf16 hi/lo (q pre-scaled)
    {
        dim3 grid(N_QKV / 128, MTOT / 128);
        gemm_mma_kernel<true><<<grid, 256, GEMM_SMEM>>>(
            xh, xl, wqh, wql, b_qkv, nullptr,
            qh, ql, kh, kl, vh, vl, MTOT, N_QKV, DMODEL);
    }
    // 2) Tensor-core flash attention -> ctx hi/lo
    {
        dim3 grid(SEQ / 128, NHEAD, BATCH);
        flash_mma_kernel<<<grid, 256, FLASH_SMEM>>>(qh, ql, kh, kl, vh, vl, ch, cl);
    }
    // 3) Output projection -> fp32 out
    {
        dim3 grid(DMODEL / 128, MTOT / 128);
        gemm_mma_kernel<false><<<grid, 256, GEMM_SMEM>>>(
            ch, cl, woh, wol, b_out, out,
            nullptr, nullptr, nullptr, nullptr, nullptr, nullptr,
            MTOT, DMODEL, DMODEL);
    }
}

// round 10
// speedup vs baseline: 1.4287x; 1.4278x over previous
#include <cuda_runtime.h>
#include <cuda_fp16.h>
#include <math.h>
#include <stdint.h>

#define BATCH 2
#define SEQ   2048
#define DMODEL 1024
#define NHEAD 16
#define DHEAD 64
#define MTOT  (BATCH*SEQ)          // 4096
#define N_QKV (3*DMODEL)           // 3072
#define HTOT (BATCH*NHEAD)         // 32

// ---------------------------------------------------------------------------
// Scratch (__device__ globals) — fp16; A-operands split hi/lo, B-operands single
// ---------------------------------------------------------------------------
__device__ __half g_xh[(size_t)MTOT * DMODEL];
__device__ __half g_xl[(size_t)MTOT * DMODEL];
__device__ __half g_wqkvT_h[(size_t)N_QKV * DMODEL];   // [N][K] single
__device__ __half g_woutT_h[(size_t)DMODEL * DMODEL];  // single
// head-major [b,h,s,d]
__device__ __half g_qh[(size_t)HTOT * SEQ * DHEAD];    // q split
__device__ __half g_ql[(size_t)HTOT * SEQ * DHEAD];
__device__ __half g_kh[(size_t)HTOT * SEQ * DHEAD];    // k single
__device__ __half g_vh[(size_t)HTOT * SEQ * DHEAD];    // v single
// ctx split
__device__ __half g_ctxh[(size_t)MTOT * DMODEL];
__device__ __half g_ctxl[(size_t)MTOT * DMODEL];

// ---------------------------------------------------------------------------
// Helpers
// ---------------------------------------------------------------------------
__device__ __forceinline__ uint32_t smem_to_u32(const void* p) {
    uint32_t a;
    asm("{ .reg .u64 t; cvta.to.shared.u64 t, %1; cvt.u32.u64 %0, t; }" : "=r"(a) : "l"(p));
    return a;
}
__device__ __forceinline__ void ldsm_x4(uint32_t& r0, uint32_t& r1, uint32_t& r2,
                                        uint32_t& r3, uint32_t addr) {
    asm volatile("ldmatrix.sync.aligned.m8n8.x4.shared.b16 {%0,%1,%2,%3}, [%4];"
                 : "=r"(r0), "=r"(r1), "=r"(r2), "=r"(r3) : "r"(addr));
}
__device__ __forceinline__ void ldsm_x4t(uint32_t& r0, uint32_t& r1, uint32_t& r2,
                                         uint32_t& r3, uint32_t addr) {
    asm volatile("ldmatrix.sync.aligned.m8n8.x4.trans.shared.b16 {%0,%1,%2,%3}, [%4];"
                 : "=r"(r0), "=r"(r1), "=r"(r2), "=r"(r3) : "r"(addr));
}
__device__ __forceinline__ void mma_f16(float* c, const uint32_t* a, const uint32_t* b) {
    asm volatile(
        "mma.sync.aligned.m16n8k16.row.col.f32.f16.f16.f32 "
        "{%0,%1,%2,%3}, {%4,%5,%6,%7}, {%8,%9}, {%0,%1,%2,%3};"
        : "+f"(c[0]), "+f"(c[1]), "+f"(c[2]), "+f"(c[3])
        : "r"(a[0]), "r"(a[1]), "r"(a[2]), "r"(a[3]), "r"(b[0]), "r"(b[1]));
}
__device__ __forceinline__ void cp_async16(uint32_t saddr, const void* gaddr) {
    asm volatile("cp.async.cg.shared.global [%0], [%1], 16;" :: "r"(saddr), "l"(gaddr));
}
#define CP_COMMIT() asm volatile("cp.async.commit_group;" ::: "memory")
#define CP_WAIT0()  asm volatile("cp.async.wait_group 0;" ::: "memory")

// pack two fp32 -> f16x2 hi (lo half = x) + residual f16x2 lo
__device__ __forceinline__ void pack_split(float x, float y, uint32_t& hi, uint32_t& lo) {
    __half2 h2 = __floats2half2_rn(x, y);
    float2 f = __half22float2(h2);
    __half2 l2 = __floats2half2_rn(x - f.x, y - f.y);
    hi = *reinterpret_cast<uint32_t*>(&h2);
    lo = *reinterpret_cast<uint32_t*>(&l2);
}
__device__ __forceinline__ uint32_t pack2(float x, float y) {
    __half2 h2 = __floats2half2_rn(x, y);
    return *reinterpret_cast<uint32_t*>(&h2);
}

// ---------------------------------------------------------------------------
// fp32 -> (hi, lo) fp16 split (for x)
// ---------------------------------------------------------------------------
__global__ void convert_split_kernel(const float* __restrict__ in,
                                     __half* __restrict__ oh,
                                     __half* __restrict__ ol, int n4)
{
    for (int i = blockIdx.x * blockDim.x + threadIdx.x; i < n4; i += gridDim.x * blockDim.x) {
        float4 v = *(const float4*)(in + (size_t)i * 4);
        uint32_t h0, l0, h1, l1;
        pack_split(v.x, v.y, h0, l0);
        pack_split(v.z, v.w, h1, l1);
        uint32_t* ph = (uint32_t*)(oh + (size_t)i * 4);
        uint32_t* pl = (uint32_t*)(ol + (size_t)i * 4);
        ph[0] = h0; ph[1] = h1;
        pl[0] = l0; pl[1] = l1;
    }
}

// ---------------------------------------------------------------------------
// w[K][N] fp32 -> wT [N][K] fp16 (single, hi only)
// ---------------------------------------------------------------------------
__global__ void transpose_half_kernel(const float* __restrict__ w,
                                      __half* __restrict__ th,
                                      int K, int N)
{
    __shared__ float tile[32][33];
    const int tx = threadIdx.x, ty = threadIdx.y;
    const int x0 = blockIdx.x * 32;
    const int y0 = blockIdx.y * 32;
    #pragma unroll
    for (int i = 0; i < 4; i++) {
        int kl = ty + i * 8;
        tile[kl][tx] = w[(size_t)(y0 + kl) * N + x0 + tx];
    }
    __syncthreads();
    #pragma unroll
    for (int i = 0; i < 4; i++) {
        int nl = ty + i * 8;
        th[(size_t)(x0 + nl) * K + y0 + tx] = __float2half_rn(tile[tx][nl]);
    }
}

// ---------------------------------------------------------------------------
// fp16 2-term GEMM (mma.sync): C = (Ah+Al) @ Bh^T (+bias)
// CTA 128x128 BK32, 8 warps, double-buffered cp.async. 3 tiles/stage.
// ---------------------------------------------------------------------------
#define TILE_B   (128 * 80)
#define STAGE_B  (3 * TILE_B)

template<bool QKV_EPI>
__global__ __launch_bounds__(256)
void gemm_mma_kernel(const __half* __restrict__ Ah, const __half* __restrict__ Al,
                     const __half* __restrict__ Bh,
                     const float* __restrict__ bias, float* __restrict__ C,
                     __half* __restrict__ qh, __half* __restrict__ ql,
                     __half* __restrict__ kh, __half* __restrict__ vh,
                     int M, int N, int K)
{
    extern __shared__ __align__(16) char smem[];
    const uint32_t sbase = smem_to_u32(smem);

    const int tid = threadIdx.x;
    const int lane = tid & 31;
    const int wid = tid >> 5;
    const int warp_m = wid >> 2;
    const int warp_n = wid & 3;
    const int bM = blockIdx.y * 128, bN = blockIdx.x * 128;

    const int grow = tid >> 2;
    const int gslot = tid & 3;
    const int NT = K / 32;

    auto issue = [&](int t) {
        const uint32_t sb = sbase + (t & 1) * STAGE_B;
        const int kof = t * 32 + gslot * 8;
        #pragma unroll
        for (int p = 0; p < 2; p++) {
            const int r = grow + p * 64;
            const uint32_t so = (uint32_t)(r * 80 + gslot * 16);
            cp_async16(sb + so,              Ah + (size_t)(bM + r) * K + kof);
            cp_async16(sb + TILE_B + so,     Al + (size_t)(bM + r) * K + kof);
            cp_async16(sb + 2 * TILE_B + so, Bh + (size_t)(bN + r) * K + kof);
        }
        CP_COMMIT();
    };

    float acc[4][4][4];
    #pragma unroll
    for (int i = 0; i < 4; i++)
        #pragma unroll
        for (int j = 0; j < 4; j++)
            #pragma unroll
            for (int k = 0; k < 4; k++) acc[i][j][k] = 0.f;

    issue(0);

    const int a_row = (lane & 7) + ((lane >> 3) & 1) * 8;
    const int a_sel = (lane >> 4);
    const int b_row = (lane & 7) + ((lane >> 4) << 3);
    const int b_sel = (lane >> 3) & 1;

    for (int t = 0; t < NT; t++) {
        CP_WAIT0();
        __syncthreads();
        if (t + 1 < NT) issue(t + 1);

        const uint32_t sb  = sbase + (t & 1) * STAGE_B;
        const uint32_t sAh = sb, sAl = sb + TILE_B, sBh = sb + 2 * TILE_B;

        #pragma unroll
        for (int kk = 0; kk < 2; kk++) {
            uint32_t bh[8];
            {
                const uint32_t ba = (uint32_t)((warp_n * 32 + b_row) * 80 + kk * 32 + b_sel * 16);
                ldsm_x4(bh[0], bh[1], bh[2], bh[3], sBh + ba);
                ldsm_x4(bh[4], bh[5], bh[6], bh[7], sBh + ba + 16 * 80);
            }
            #pragma unroll
            for (int mt = 0; mt < 4; mt++) {
                const uint32_t aa = (uint32_t)((warp_m * 64 + mt * 16 + a_row) * 80
                                               + kk * 32 + a_sel * 16);
                uint32_t ah[4], al[4];
                ldsm_x4(ah[0], ah[1], ah[2], ah[3], sAh + aa);
                ldsm_x4(al[0], al[1], al[2], al[3], sAl + aa);
                // 2-term split, chain distance 4
                mma_f16(acc[mt][0], ah, &bh[0]);
                mma_f16(acc[mt][1], ah, &bh[2]);
                mma_f16(acc[mt][2], ah, &bh[4]);
                mma_f16(acc[mt][3], ah, &bh[6]);
                mma_f16(acc[mt][0], al, &bh[0]);
                mma_f16(acc[mt][1], al, &bh[2]);
                mma_f16(acc[mt][2], al, &bh[4]);
                mma_f16(acc[mt][3], al, &bh[6]);
            }
        }
    }

    if (QKV_EPI) {
        const int tensor = bN >> 10;       // 0=q, 1=k, 2=v
        const int bb = bM >> 11;
        #pragma unroll
        for (int mt = 0; mt < 4; mt++) {
            const int srow = (bM & 2047) + warp_m * 64 + mt * 16 + (lane >> 2);
            #pragma unroll
            for (int nt = 0; nt < 4; nt++) {
                const int cg = bN + warp_n * 32 + nt * 8 + (lane & 3) * 2;
                const int hh = (cg & 1023) >> 6;
                const int d  = cg & 63;
                const size_t base = ((size_t)(bb * NHEAD + hh) * SEQ) * DHEAD + d;
                const float v0 = acc[mt][nt][0] + bias[cg];
                const float v1 = acc[mt][nt][1] + bias[cg + 1];
                const float v2 = acc[mt][nt][2] + bias[cg];
                const float v3 = acc[mt][nt][3] + bias[cg + 1];
                if (tensor == 0) {
                    uint32_t h0, l0, h1, l1;
                    pack_split(v0, v1, h0, l0);
                    pack_split(v2, v3, h1, l1);
                    *(uint32_t*)(qh + base + (size_t)srow * DHEAD)       = h0;
                    *(uint32_t*)(ql + base + (size_t)srow * DHEAD)       = l0;
                    *(uint32_t*)(qh + base + (size_t)(srow + 8) * DHEAD) = h1;
                    *(uint32_t*)(ql + base + (size_t)(srow + 8) * DHEAD) = l1;
                } else {
                    __half* dst = (tensor == 1) ? kh : vh;
                    *(uint32_t*)(dst + base + (size_t)srow * DHEAD)       = pack2(v0, v1);
                    *(uint32_t*)(dst + base + (size_t)(srow + 8) * DHEAD) = pack2(v2, v3);
                }
            }
        }
    } else {
        #pragma unroll
        for (int mt = 0; mt < 4; mt++) {
            const int r0 = bM + warp_m * 64 + mt * 16 + (lane >> 2);
            #pragma unroll
            for (int nt = 0; nt < 4; nt++) {
                const int c = bN + warp_n * 32 + nt * 8 + (lane & 3) * 2;
                const float bx = bias[c], by = bias[c + 1];
                *(float2*)(C + (size_t)r0 * N + c) =
                    make_float2(acc[mt][nt][0] + bx, acc[mt][nt][1] + by);
                *(float2*)(C + (size_t)(r0 + 8) * N + c) =
                    make_float2(acc[mt][nt][2] + bx, acc[mt][nt][3] + by);
            }
        }
    }
}

// ---------------------------------------------------------------------------
// Tensor-core flash attention, fp16 2-term. Q split (hi/lo), K/V single.
// smem: Q hi/lo + 2-stage double-buffered K,V = 6 tiles (110KB).
// Softmax scale folded in (q stored unscaled to keep ql in normal fp16 range).
// ---------------------------------------------------------------------------
#define FS_TILE 18432            // 128 rows * 144B

__global__ __launch_bounds__(256, 1)
void flash_mma_kernel(const __half* __restrict__ qh, const __half* __restrict__ ql,
                      const __half* __restrict__ kh, const __half* __restrict__ vh,
                      __half* __restrict__ ctxh, __half* __restrict__ ctxl)
{
    extern __shared__ __align__(16) char smem[];
    const uint32_t sb = smem_to_u32(smem);
    const uint32_t QH = sb, QL = sb + FS_TILE;
    const int tid = threadIdx.x;
    const int lane = tid & 31;
    const int wid = tid >> 5;
    const int mrow = wid * 16;

    const int qt = blockIdx.x;
    const int bh = blockIdx.z * NHEAD + blockIdx.y;
    const int q0 = qt * 128;

    const size_t headbase = (size_t)bh * SEQ * DHEAD;

    const int gr = tid >> 1;
    const int gc = (tid & 1) * 4;
    const uint32_t gso = (uint32_t)(gr * 144 + gc * 16);

    // Q load (hi + lo)
    {
        const __half* pqh = qh + headbase + (size_t)(q0 + gr) * DHEAD + gc * 8;
        const __half* pql = ql + headbase + (size_t)(q0 + gr) * DHEAD + gc * 8;
        #pragma unroll
        for (int c = 0; c < 4; c++) {
            cp_async16(QH + gso + c * 16, pqh + c * 8);
            cp_async16(QL + gso + c * 16, pql + c * 8);
        }
        CP_COMMIT();
    }

    auto loadKV = [&](int t) {
        const uint32_t bk = sb + 2 * FS_TILE + (t & 1) * 2 * FS_TILE;
        const uint32_t bv = bk + FS_TILE;
        const size_t g = headbase + (size_t)(t * 128 + gr) * DHEAD + gc * 8;
        #pragma unroll
        for (int c = 0; c < 4; c++) {
            cp_async16(bk + gso + c * 16, kh + g + c * 8);
            cp_async16(bv + gso + c * 16, vh + g + c * 8);
        }
        CP_COMMIT();
    };
    loadKV(0);

    const int arow = (lane & 7) + ((lane >> 3) & 1) * 8;
    const int asel = (lane >> 4);
    const int brow = (lane & 7) + ((lane >> 4) << 3);
    const int bsel = (lane >> 3) & 1;
    const uint32_t a_off = (uint32_t)((mrow + arow) * 144 + asel * 16);
    const uint32_t b_off = (uint32_t)(brow * 144 + bsel * 16);
    const uint32_t v_off = (uint32_t)(arow * 144 + asel * 16);

    uint32_t qfh[4][4], qfl[4][4];

    float m0 = -INFINITY, m1 = -INFINITY, l0 = 0.f, l1 = 0.f;
    float oacc[8][4];
    #pragma unroll
    for (int i = 0; i < 8; i++)
        #pragma unroll
        for (int j = 0; j < 4; j++) oacc[i][j] = 0.f;

    const int NTK = SEQ / 128;
    for (int t = 0; t < NTK; t++) {
        CP_WAIT0();
        __syncthreads();
        if (t + 1 < NTK) loadKV(t + 1);

        if (t == 0) {
            #pragma unroll
            for (int ks = 0; ks < 4; ks++) {
                ldsm_x4(qfh[ks][0], qfh[ks][1], qfh[ks][2], qfh[ks][3], QH + a_off + ks * 32);
                ldsm_x4(qfl[ks][0], qfl[ks][1], qfl[ks][2], qfl[ks][3], QL + a_off + ks * 32);
            }
        }

        const uint32_t KHB = sb + 2 * FS_TILE + (t & 1) * 2 * FS_TILE;
        const uint32_t VHB = KHB + FS_TILE;

        // ---- S = Q K^T (2-term: qh·k + ql·k) ----
        float sacc[16][4];
        #pragma unroll
        for (int i = 0; i < 16; i++)
            #pragma unroll
            for (int j = 0; j < 4; j++) sacc[i][j] = 0.f;

        #pragma unroll
        for (int ks = 0; ks < 4; ks++) {
            #pragma unroll
            for (int npp = 0; npp < 4; npp++) {
                uint32_t kbh[8];
                const uint32_t ko = b_off + (uint32_t)(npp * 2 * 2304 + ks * 32);
                ldsm_x4(kbh[0], kbh[1], kbh[2], kbh[3], KHB + ko);
                ldsm_x4(kbh[4], kbh[5], kbh[6], kbh[7], KHB + ko + 2304);
                float* s0 = sacc[npp * 4 + 0];
                float* s1 = sacc[npp * 4 + 1];
                float* s2 = sacc[npp * 4 + 2];
                float* s3 = sacc[npp * 4 + 3];
                mma_f16(s0, qfh[ks], &kbh[0]);
                mma_f16(s1, qfh[ks], &kbh[2]);
                mma_f16(s2, qfh[ks], &kbh[4]);
                mma_f16(s3, qfh[ks], &kbh[6]);
                mma_f16(s0, qfl[ks], &kbh[0]);
                mma_f16(s1, qfl[ks], &kbh[2]);
                mma_f16(s2, qfl[ks], &kbh[4]);
                mma_f16(s3, qfl[ks], &kbh[6]);
            }
        }

        // apply softmax scale (q stored unscaled)
        #pragma unroll
        for (int i = 0; i < 16; i++) {
            sacc[i][0] *= 0.125f; sacc[i][1] *= 0.125f;
            sacc[i][2] *= 0.125f; sacc[i][3] *= 0.125f;
        }

        // ---- online softmax ----
        float mx0 = -INFINITY, mx1 = -INFINITY;
        #pragma unroll
        for (int i = 0; i < 16; i++) {
            mx0 = fmaxf(mx0, fmaxf(sacc[i][0], sacc[i][1]));
            mx1 = fmaxf(mx1, fmaxf(sacc[i][2], sacc[i][3]));
        }
        mx0 = fmaxf(mx0, __shfl_xor_sync(0xffffffffu, mx0, 1));
        mx0 = fmaxf(mx0, __shfl_xor_sync(0xffffffffu, mx0, 2));
        mx1 = fmaxf(mx1, __shfl_xor_sync(0xffffffffu, mx1, 1));
        mx1 = fmaxf(mx1, __shfl_xor_sync(0xffffffffu, mx1, 2));
        const float mn0 = fmaxf(m0, mx0), mn1 = fmaxf(m1, mx1);
        const float c0 = __expf(m0 - mn0), c1 = __expf(m1 - mn1);
        m0 = mn0; m1 = mn1;

        float ps0 = 0.f, ps1 = 0.f;
        #pragma unroll
        for (int i = 0; i < 16; i++) {
            sacc[i][0] = __expf(sacc[i][0] - mn0); ps0 += sacc[i][0];
            sacc[i][1] = __expf(sacc[i][1] - mn0); ps0 += sacc[i][1];
            sacc[i][2] = __expf(sacc[i][2] - mn1); ps1 += sacc[i][2];
            sacc[i][3] = __expf(sacc[i][3] - mn1); ps1 += sacc[i][3];
        }
        ps0 += __shfl_xor_sync(0xffffffffu, ps0, 1);
        ps0 += __shfl_xor_sync(0xffffffffu, ps0, 2);
        ps1 += __shfl_xor_sync(0xffffffffu, ps1, 1);
        ps1 += __shfl_xor_sync(0xffffffffu, ps1, 2);
        l0 = l0 * c0 + ps0;
        l1 = l1 * c1 + ps1;

        #pragma unroll
        for (int i = 0; i < 8; i++) {
            oacc[i][0] *= c0; oacc[i][1] *= c0;
            oacc[i][2] *= c1; oacc[i][3] *= c1;
        }

        // ---- O += P V (2-term: Ph·V + Pl·V) ----
        #pragma unroll
        for (int ks = 0; ks < 8; ks++) {
            uint32_t ah[4], al[4];
            pack_split(sacc[2 * ks][0],     sacc[2 * ks][1],     ah[0], al[0]);
            pack_split(sacc[2 * ks][2],     sacc[2 * ks][3],     ah[1], al[1]);
            pack_split(sacc[2 * ks + 1][0], sacc[2 * ks + 1][1], ah[2], al[2]);
            pack_split(sacc[2 * ks + 1][2], sacc[2 * ks + 1][3], ah[3], al[3]);
            #pragma unroll
            for (int ntp = 0; ntp < 2; ntp++) {
                uint32_t vbh[8];
                const uint32_t vo = v_off + (uint32_t)(ks * 2304 + ntp * 64);
                ldsm_x4t(vbh[0], vbh[1], vbh[2], vbh[3], VHB + vo);
                ldsm_x4t(vbh[4], vbh[5], vbh[6], vbh[7], VHB + vo + 32);
                float* o0 = oacc[ntp * 4 + 0];
                float* o1 = oacc[ntp * 4 + 1];
                float* o2 = oacc[ntp * 4 + 2];
                float* o3 = oacc[ntp * 4 + 3];
                mma_f16(o0, ah, &vbh[0]);
                mma_f16(o1, ah, &vbh[2]);
                mma_f16(o2, ah, &vbh[4]);
                mma_f16(o3, ah, &vbh[6]);
                mma_f16(o0, al, &vbh[0]);
                mma_f16(o1, al, &vbh[2]);
                mma_f16(o2, al, &vbh[4]);
                mma_f16(o3, al, &vbh[6]);
            }
        }
    }

    // ---- epilogue: normalize, split, write ctx ----
    const float inv0 = 1.f / l0, inv1 = 1.f / l1;
    const int row0 = q0 + mrow + (lane >> 2);
    const size_t base0 = ((size_t)blockIdx.z * SEQ + row0) * DMODEL
                         + blockIdx.y * DHEAD + (lane & 3) * 2;
    const size_t base1 = base0 + 8 * DMODEL;
    #pragma unroll
    for (int nt = 0; nt < 8; nt++) {
        uint32_t h, l;
        pack_split(oacc[nt][0] * inv0, oacc[nt][1] * inv0, h, l);
        *(uint32_t*)(ctxh + base0 + nt * 8) = h;
        *(uint32_t*)(ctxl + base0 + nt * 8) = l;
        pack_split(oacc[nt][2] * inv1, oacc[nt][3] * inv1, h, l);
        *(uint32_t*)(ctxh + base1 + nt * 8) = h;
        *(uint32_t*)(ctxl + base1 + nt * 8) = l;
    }
}

// ---------------------------------------------------------------------------
extern "C" void kernel_launch(void* const* d_in, const int* in_sizes, int n_in,
                              void* d_out, int out_size)
{
    const float* x      = (const float*)d_in[0];
    const float* w_qkv  = (const float*)d_in[1];
    const float* b_qkv  = (const float*)d_in[2];
    const float* w_out  = (const float*)d_in[3];
    const float* b_out  = (const float*)d_in[4];
    float* out = (float*)d_out;

    __half *xh, *xl, *wqh, *woh;
    __half *qh, *ql, *kh, *vh, *ch, *cl;
    cudaGetSymbolAddress((void**)&xh, g_xh);
    cudaGetSymbolAddress((void**)&xl, g_xl);
    cudaGetSymbolAddress((void**)&wqh, g_wqkvT_h);
    cudaGetSymbolAddress((void**)&woh, g_woutT_h);
    cudaGetSymbolAddress((void**)&qh, g_qh);
    cudaGetSymbolAddress((void**)&ql, g_ql);
    cudaGetSymbolAddress((void**)&kh, g_kh);
    cudaGetSymbolAddress((void**)&vh, g_vh);
    cudaGetSymbolAddress((void**)&ch, g_ctxh);
    cudaGetSymbolAddress((void**)&cl, g_ctxl);

    const int GEMM_SMEM  = 2 * STAGE_B;    // 61440
    const int FLASH_SMEM = 6 * FS_TILE;    // 110592
    cudaFuncSetAttribute(gemm_mma_kernel<true>,
                         cudaFuncAttributeMaxDynamicSharedMemorySize, GEMM_SMEM);
    cudaFuncSetAttribute(gemm_mma_kernel<false>,
                         cudaFuncAttributeMaxDynamicSharedMemorySize, GEMM_SMEM);
    cudaFuncSetAttribute(flash_mma_kernel,
                         cudaFuncAttributeMaxDynamicSharedMemorySize, FLASH_SMEM);

    // 0) conversions (weights single fp16 now — half the work)
    convert_split_kernel<<<2048, 256>>>(x, xh, xl, MTOT * DMODEL / 4);
    transpose_half_kernel<<<dim3(N_QKV / 32, DMODEL / 32), dim3(32, 8)>>>(
        w_qkv, wqh, DMODEL, N_QKV);
    transpose_half_kernel<<<dim3(DMODEL / 32, DMODEL / 32), dim3(32, 8)>>>(
        w_out, woh, DMODEL, DMODEL);

    // 1) QKV projection -> q split / k,v single (head-major)
    {
        dim3 grid(N_QKV / 128, MTOT / 128);
        gemm_mma_kernel<true><<<grid, 256, GEMM_SMEM>>>(
            xh, xl, wqh, b_qkv, nullptr,
            qh, ql, kh, vh, MTOT, N_QKV, DMODEL);
    }
    // 2) Tensor-core flash attention -> ctx split
    {
        dim3 grid(SEQ / 128, NHEAD, BATCH);
        flash_mma_kernel<<<grid, 256, FLASH_SMEM>>>(qh, ql, kh, vh, ch, cl);
    }
    // 3) Output projection -> fp32 out
    {
        dim3 grid(DMODEL / 128, MTOT / 128);
        gemm_mma_kernel<false><<<grid, 256, GEMM_SMEM>>>(
            ch, cl, woh, b_out, out,
            nullptr, nullptr, nullptr, nullptr, MTOT, DMODEL, DMODEL);
    }
}

// round 11
// speedup vs baseline: 2.1068x; 1.4746x over previous
#include <cuda_runtime.h>
#include <cuda_fp16.h>
#include <math.h>
#include <stdint.h>

#define BATCH 2
#define SEQ   2048
#define DMODEL 1024
#define NHEAD 16
#define DHEAD 64
#define MTOT  (BATCH*SEQ)          // 4096
#define N_QKV (3*DMODEL)           // 3072
#define HTOT (BATCH*NHEAD)         // 32

// ---------------------------------------------------------------------------
// Scratch (__device__ globals) — all single fp16
// ---------------------------------------------------------------------------
__device__ __half g_x16[(size_t)MTOT * DMODEL];
__device__ __half g_wqkvT[(size_t)N_QKV * DMODEL];    // [N][K]
__device__ __half g_woutT[(size_t)DMODEL * DMODEL];
// head-major [b,h,s,d]
__device__ __half g_q16[(size_t)HTOT * SEQ * DHEAD];  // unscaled
__device__ __half g_k16[(size_t)HTOT * SEQ * DHEAD];
__device__ __half g_v16[(size_t)HTOT * SEQ * DHEAD];
// ctx [b,s,(h,d)]
__device__ __half g_ctx[(size_t)MTOT * DMODEL];

// ---------------------------------------------------------------------------
// Helpers
// ---------------------------------------------------------------------------
__device__ __forceinline__ uint32_t smem_to_u32(const void* p) {
    uint32_t a;
    asm("{ .reg .u64 t; cvta.to.shared.u64 t, %1; cvt.u32.u64 %0, t; }" : "=r"(a) : "l"(p));
    return a;
}
__device__ __forceinline__ void ldsm_x4(uint32_t& r0, uint32_t& r1, uint32_t& r2,
                                        uint32_t& r3, uint32_t addr) {
    asm volatile("ldmatrix.sync.aligned.m8n8.x4.shared.b16 {%0,%1,%2,%3}, [%4];"
                 : "=r"(r0), "=r"(r1), "=r"(r2), "=r"(r3) : "r"(addr));
}
__device__ __forceinline__ void ldsm_x4t(uint32_t& r0, uint32_t& r1, uint32_t& r2,
                                         uint32_t& r3, uint32_t addr) {
    asm volatile("ldmatrix.sync.aligned.m8n8.x4.trans.shared.b16 {%0,%1,%2,%3}, [%4];"
                 : "=r"(r0), "=r"(r1), "=r"(r2), "=r"(r3) : "r"(addr));
}
__device__ __forceinline__ void mma_f16(float* c, const uint32_t* a, const uint32_t* b) {
    asm volatile(
        "mma.sync.aligned.m16n8k16.row.col.f32.f16.f16.f32 "
        "{%0,%1,%2,%3}, {%4,%5,%6,%7}, {%8,%9}, {%0,%1,%2,%3};"
        : "+f"(c[0]), "+f"(c[1]), "+f"(c[2]), "+f"(c[3])
        : "r"(a[0]), "r"(a[1]), "r"(a[2]), "r"(a[3]), "r"(b[0]), "r"(b[1]));
}
__device__ __forceinline__ void cp_async16(uint32_t saddr, const void* gaddr) {
    asm volatile("cp.async.cg.shared.global [%0], [%1], 16;" :: "r"(saddr), "l"(gaddr));
}
#define CP_COMMIT() asm volatile("cp.async.commit_group;" ::: "memory")
#define CP_WAIT0()  asm volatile("cp.async.wait_group 0;" ::: "memory")

__device__ __forceinline__ uint32_t pack2(float x, float y) {
    __half2 h2 = __floats2half2_rn(x, y);
    return *reinterpret_cast<uint32_t*>(&h2);
}

// ---------------------------------------------------------------------------
// fp32 -> fp16 (for x)
// ---------------------------------------------------------------------------
__global__ void convert_half_kernel(const float* __restrict__ in,
                                    __half* __restrict__ o, int n4)
{
    for (int i = blockIdx.x * blockDim.x + threadIdx.x; i < n4; i += gridDim.x * blockDim.x) {
        float4 v = *(const float4*)(in + (size_t)i * 4);
        uint32_t* p = (uint32_t*)(o + (size_t)i * 4);
        p[0] = pack2(v.x, v.y);
        p[1] = pack2(v.z, v.w);
    }
}

// ---------------------------------------------------------------------------
// w[K][N] fp32 -> wT [N][K] fp16
// ---------------------------------------------------------------------------
__global__ void transpose_half_kernel(const float* __restrict__ w,
                                      __half* __restrict__ th,
                                      int K, int N)
{
    __shared__ float tile[32][33];
    const int tx = threadIdx.x, ty = threadIdx.y;
    const int x0 = blockIdx.x * 32;
    const int y0 = blockIdx.y * 32;
    #pragma unroll
    for (int i = 0; i < 4; i++) {
        int kl = ty + i * 8;
        tile[kl][tx] = w[(size_t)(y0 + kl) * N + x0 + tx];
    }
    __syncthreads();
    #pragma unroll
    for (int i = 0; i < 4; i++) {
        int nl = ty + i * 8;
        th[(size_t)(x0 + nl) * K + y0 + tx] = __float2half_rn(tile[tx][nl]);
    }
}

// ---------------------------------------------------------------------------
// fp16 GEMM (mma.sync): C = A @ B^T (+bias)
// CTA 128x128 BK32, 8 warps, double-buffered cp.async. 2 tiles/stage.
// ---------------------------------------------------------------------------
#define TILE_B   (128 * 80)
#define STAGE_B  (2 * TILE_B)

template<bool QKV_EPI>
__global__ __launch_bounds__(256)
void gemm_mma_kernel(const __half* __restrict__ A, const __half* __restrict__ B,
                     const float* __restrict__ bias, float* __restrict__ C,
                     __half* __restrict__ q16, __half* __restrict__ k16,
                     __half* __restrict__ v16,
                     int M, int N, int K)
{
    extern __shared__ __align__(16) char smem[];
    const uint32_t sbase = smem_to_u32(smem);

    const int tid = threadIdx.x;
    const int lane = tid & 31;
    const int wid = tid >> 5;
    const int warp_m = wid >> 2;
    const int warp_n = wid & 3;
    const int bM = blockIdx.y * 128, bN = blockIdx.x * 128;

    const int grow = tid >> 2;
    const int gslot = tid & 3;
    const int NT = K / 32;

    auto issue = [&](int t) {
        const uint32_t sb = sbase + (t & 1) * STAGE_B;
        const int kof = t * 32 + gslot * 8;
        #pragma unroll
        for (int p = 0; p < 2; p++) {
            const int r = grow + p * 64;
            const uint32_t so = (uint32_t)(r * 80 + gslot * 16);
            cp_async16(sb + so,          A + (size_t)(bM + r) * K + kof);
            cp_async16(sb + TILE_B + so, B + (size_t)(bN + r) * K + kof);
        }
        CP_COMMIT();
    };

    float acc[4][4][4];
    #pragma unroll
    for (int i = 0; i < 4; i++)
        #pragma unroll
        for (int j = 0; j < 4; j++)
            #pragma unroll
            for (int k = 0; k < 4; k++) acc[i][j][k] = 0.f;

    issue(0);

    const int a_row = (lane & 7) + ((lane >> 3) & 1) * 8;
    const int a_sel = (lane >> 4);
    const int b_row = (lane & 7) + ((lane >> 4) << 3);
    const int b_sel = (lane >> 3) & 1;

    for (int t = 0; t < NT; t++) {
        CP_WAIT0();
        __syncthreads();
        if (t + 1 < NT) issue(t + 1);

        const uint32_t sb = sbase + (t & 1) * STAGE_B;
        const uint32_t sA = sb, sB = sb + TILE_B;

        #pragma unroll
        for (int kk = 0; kk < 2; kk++) {
            uint32_t bh[8];
            {
                const uint32_t ba = (uint32_t)((warp_n * 32 + b_row) * 80 + kk * 32 + b_sel * 16);
                ldsm_x4(bh[0], bh[1], bh[2], bh[3], sB + ba);
                ldsm_x4(bh[4], bh[5], bh[6], bh[7], sB + ba + 16 * 80);
            }
            #pragma unroll
            for (int mt = 0; mt < 4; mt++) {
                const uint32_t aa = (uint32_t)((warp_m * 64 + mt * 16 + a_row) * 80
                                               + kk * 32 + a_sel * 16);
                uint32_t ah[4];
                ldsm_x4(ah[0], ah[1], ah[2], ah[3], sA + aa);
                mma_f16(acc[mt][0], ah, &bh[0]);
                mma_f16(acc[mt][1], ah, &bh[2]);
                mma_f16(acc[mt][2], ah, &bh[4]);
                mma_f16(acc[mt][3], ah, &bh[6]);
            }
        }
    }

    if (QKV_EPI) {
        const int tensor = bN >> 10;       // 0=q, 1=k, 2=v
        __half* dst = (tensor == 0) ? q16 : (tensor == 1) ? k16 : v16;
        const int bb = bM >> 11;
        #pragma unroll
        for (int mt = 0; mt < 4; mt++) {
            const int srow = (bM & 2047) + warp_m * 64 + mt * 16 + (lane >> 2);
            #pragma unroll
            for (int nt = 0; nt < 4; nt++) {
                const int cg = bN + warp_n * 32 + nt * 8 + (lane & 3) * 2;
                const int hh = (cg & 1023) >> 6;
                const int d  = cg & 63;
                const size_t base = ((size_t)(bb * NHEAD + hh) * SEQ) * DHEAD + d;
                *(uint32_t*)(dst + base + (size_t)srow * DHEAD) =
                    pack2(acc[mt][nt][0] + bias[cg], acc[mt][nt][1] + bias[cg + 1]);
                *(uint32_t*)(dst + base + (size_t)(srow + 8) * DHEAD) =
                    pack2(acc[mt][nt][2] + bias[cg], acc[mt][nt][3] + bias[cg + 1]);
            }
        }
    } else {
        #pragma unroll
        for (int mt = 0; mt < 4; mt++) {
            const int r0 = bM + warp_m * 64 + mt * 16 + (lane >> 2);
            #pragma unroll
            for (int nt = 0; nt < 4; nt++) {
                const int c = bN + warp_n * 32 + nt * 8 + (lane & 3) * 2;
                const float bx = bias[c], by = bias[c + 1];
                *(float2*)(C + (size_t)r0 * N + c) =
                    make_float2(acc[mt][nt][0] + bx, acc[mt][nt][1] + by);
                *(float2*)(C + (size_t)(r0 + 8) * N + c) =
                    make_float2(acc[mt][nt][2] + bx, acc[mt][nt][3] + by);
            }
        }
    }
}

// ---------------------------------------------------------------------------
// Tensor-core flash attention, all single fp16.
// smem: Q (1 tile) + double-buffered K,V (4 tiles) = 92KB.
// Softmax scale applied to scores (q stored unscaled).
// ---------------------------------------------------------------------------
#define FS_TILE 18432            // 128 rows * 144B

__global__ __launch_bounds__(256, 1)
void flash_mma_kernel(const __half* __restrict__ q16, const __half* __restrict__ k16,
                      const __half* __restrict__ v16,
                      __half* __restrict__ ctx)
{
    extern __shared__ __align__(16) char smem[];
    const uint32_t sb = smem_to_u32(smem);
    const uint32_t QS = sb;
    const int tid = threadIdx.x;
    const int lane = tid & 31;
    const int wid = tid >> 5;
    const int mrow = wid * 16;

    const int qt = blockIdx.x;
    const int bh = blockIdx.z * NHEAD + blockIdx.y;
    const int q0 = qt * 128;

    const size_t headbase = (size_t)bh * SEQ * DHEAD;

    const int gr = tid >> 1;
    const int gc = (tid & 1) * 4;
    const uint32_t gso = (uint32_t)(gr * 144 + gc * 16);

    // Q load
    {
        const __half* pq = q16 + headbase + (size_t)(q0 + gr) * DHEAD + gc * 8;
        #pragma unroll
        for (int c = 0; c < 4; c++)
            cp_async16(QS + gso + c * 16, pq + c * 8);
        CP_COMMIT();
    }

    auto loadKV = [&](int t) {
        const uint32_t bk = sb + FS_TILE + (t & 1) * 2 * FS_TILE;
        const uint32_t bv = bk + FS_TILE;
        const size_t g = headbase + (size_t)(t * 128 + gr) * DHEAD + gc * 8;
        #pragma unroll
        for (int c = 0; c < 4; c++) {
            cp_async16(bk + gso + c * 16, k16 + g + c * 8);
            cp_async16(bv + gso + c * 16, v16 + g + c * 8);
        }
        CP_COMMIT();
    };
    loadKV(0);

    const int arow = (lane & 7) + ((lane >> 3) & 1) * 8;
    const int asel = (lane >> 4);
    const int brow = (lane & 7) + ((lane >> 4) << 3);
    const int bsel = (lane >> 3) & 1;
    const uint32_t a_off = (uint32_t)((mrow + arow) * 144 + asel * 16);
    const uint32_t b_off = (uint32_t)(brow * 144 + bsel * 16);
    const uint32_t v_off = (uint32_t)(arow * 144 + asel * 16);

    uint32_t qf[4][4];

    float m0 = -INFINITY, m1 = -INFINITY, l0 = 0.f, l1 = 0.f;
    float oacc[8][4];
    #pragma unroll
    for (int i = 0; i < 8; i++)
        #pragma unroll
        for (int j = 0; j < 4; j++) oacc[i][j] = 0.f;

    const int NTK = SEQ / 128;
    for (int t = 0; t < NTK; t++) {
        CP_WAIT0();
        __syncthreads();
        if (t + 1 < NTK) loadKV(t + 1);

        if (t == 0) {
            #pragma unroll
            for (int ks = 0; ks < 4; ks++)
                ldsm_x4(qf[ks][0], qf[ks][1], qf[ks][2], qf[ks][3], QS + a_off + ks * 32);
        }

        const uint32_t KHB = sb + FS_TILE + (t & 1) * 2 * FS_TILE;
        const uint32_t VHB = KHB + FS_TILE;

        // ---- S = Q K^T ----
        float sacc[16][4];
        #pragma unroll
        for (int i = 0; i < 16; i++)
            #pragma unroll
            for (int j = 0; j < 4; j++) sacc[i][j] = 0.f;

        #pragma unroll
        for (int ks = 0; ks < 4; ks++) {
            #pragma unroll
            for (int npp = 0; npp < 4; npp++) {
                uint32_t kb[8];
                const uint32_t ko = b_off + (uint32_t)(npp * 2 * 2304 + ks * 32);
                ldsm_x4(kb[0], kb[1], kb[2], kb[3], KHB + ko);
                ldsm_x4(kb[4], kb[5], kb[6], kb[7], KHB + ko + 2304);
                mma_f16(sacc[npp * 4 + 0], qf[ks], &kb[0]);
                mma_f16(sacc[npp * 4 + 1], qf[ks], &kb[2]);
                mma_f16(sacc[npp * 4 + 2], qf[ks], &kb[4]);
                mma_f16(sacc[npp * 4 + 3], qf[ks], &kb[6]);
            }
        }

        // softmax scale (q stored unscaled)
        #pragma unroll
        for (int i = 0; i < 16; i++) {
            sacc[i][0] *= 0.125f; sacc[i][1] *= 0.125f;
            sacc[i][2] *= 0.125f; sacc[i][3] *= 0.125f;
        }

        // ---- online softmax ----
        float mx0 = -INFINITY, mx1 = -INFINITY;
        #pragma unroll
        for (int i = 0; i < 16; i++) {
            mx0 = fmaxf(mx0, fmaxf(sacc[i][0], sacc[i][1]));
            mx1 = fmaxf(mx1, fmaxf(sacc[i][2], sacc[i][3]));
        }
        mx0 = fmaxf(mx0, __shfl_xor_sync(0xffffffffu, mx0, 1));
        mx0 = fmaxf(mx0, __shfl_xor_sync(0xffffffffu, mx0, 2));
        mx1 = fmaxf(mx1, __shfl_xor_sync(0xffffffffu, mx1, 1));
        mx1 = fmaxf(mx1, __shfl_xor_sync(0xffffffffu, mx1, 2));
        const float mn0 = fmaxf(m0, mx0), mn1 = fmaxf(m1, mx1);
        const float c0 = __expf(m0 - mn0), c1 = __expf(m1 - mn1);
        m0 = mn0; m1 = mn1;

        float ps0 = 0.f, ps1 = 0.f;
        #pragma unroll
        for (int i = 0; i < 16; i++) {
            sacc[i][0] = __expf(sacc[i][0] - mn0); ps0 += sacc[i][0];
            sacc[i][1] = __expf(sacc[i][1] - mn0); ps0 += sacc[i][1];
            sacc[i][2] = __expf(sacc[i][2] - mn1); ps1 += sacc[i][2];
            sacc[i][3] = __expf(sacc[i][3] - mn1); ps1 += sacc[i][3];
        }
        ps0 += __shfl_xor_sync(0xffffffffu, ps0, 1);
        ps0 += __shfl_xor_sync(0xffffffffu, ps0, 2);
        ps1 += __shfl_xor_sync(0xffffffffu, ps1, 1);
        ps1 += __shfl_xor_sync(0xffffffffu, ps1, 2);
        l0 = l0 * c0 + ps0;
        l1 = l1 * c1 + ps1;

        #pragma unroll
        for (int i = 0; i < 8; i++) {
            oacc[i][0] *= c0; oacc[i][1] *= c0;
            oacc[i][2] *= c1; oacc[i][3] *= c1;
        }

        // ---- O += P V (P single fp16) ----
        #pragma unroll
        for (int ks = 0; ks < 8; ks++) {
            uint32_t ap[4];
            ap[0] = pack2(sacc[2 * ks][0],     sacc[2 * ks][1]);
            ap[1] = pack2(sacc[2 * ks][2],     sacc[2 * ks][3]);
            ap[2] = pack2(sacc[2 * ks + 1][0], sacc[2 * ks + 1][1]);
            ap[3] = pack2(sacc[2 * ks + 1][2], sacc[2 * ks + 1][3]);
            #pragma unroll
            for (int ntp = 0; ntp < 2; ntp++) {
                uint32_t vb[8];
                const uint32_t vo = v_off + (uint32_t)(ks * 2304 + ntp * 64);
                ldsm_x4t(vb[0], vb[1], vb[2], vb[3], VHB + vo);
                ldsm_x4t(vb[4], vb[5], vb[6], vb[7], VHB + vo + 32);
                mma_f16(oacc[ntp * 4 + 0], ap, &vb[0]);
                mma_f16(oacc[ntp * 4 + 1], ap, &vb[2]);
                mma_f16(oacc[ntp * 4 + 2], ap, &vb[4]);
                mma_f16(oacc[ntp * 4 + 3], ap, &vb[6]);
            }
        }
    }

    // ---- epilogue: normalize, write ctx single fp16 ----
    const float inv0 = 1.f / l0, inv1 = 1.f / l1;
    const int row0 = q0 + mrow + (lane >> 2);
    const size_t base0 = ((size_t)blockIdx.z * SEQ + row0) * DMODEL
                         + blockIdx.y * DHEAD + (lane & 3) * 2;
    const size_t base1 = base0 + 8 * DMODEL;
    #pragma unroll
    for (int nt = 0; nt < 8; nt++) {
        *(uint32_t*)(ctx + base0 + nt * 8) = pack2(oacc[nt][0] * inv0, oacc[nt][1] * inv0);
        *(uint32_t*)(ctx + base1 + nt * 8) = pack2(oacc[nt][2] * inv1, oacc[nt][3] * inv1);
    }
}

// ---------------------------------------------------------------------------
extern "C" void kernel_launch(void* const* d_in, const int* in_sizes, int n_in,
                              void* d_out, int out_size)
{
    const float* x      = (const float*)d_in[0];
    const float* w_qkv  = (const float*)d_in[1];
    const float* b_qkv  = (const float*)d_in[2];
    const float* w_out  = (const float*)d_in[3];
    const float* b_out  = (const float*)d_in[4];
    float* out = (float*)d_out;

    __half *x16, *wq, *wo, *q16, *k16, *v16, *ctx;
    cudaGetSymbolAddress((void**)&x16, g_x16);
    cudaGetSymbolAddress((void**)&wq, g_wqkvT);
    cudaGetSymbolAddress((void**)&wo, g_woutT);
    cudaGetSymbolAddress((void**)&q16, g_q16);
    cudaGetSymbolAddress((void**)&k16, g_k16);
    cudaGetSymbolAddress((void**)&v16, g_v16);
    cudaGetSymbolAddress((void**)&ctx, g_ctx);

    const int GEMM_SMEM  = 2 * STAGE_B;    // 40960
    const int FLASH_SMEM = 5 * FS_TILE;    // 92160
    cudaFuncSetAttribute(gemm_mma_kernel<true>,
                         cudaFuncAttributeMaxDynamicSharedMemorySize, GEMM_SMEM);
    cudaFuncSetAttribute(gemm_mma_kernel<false>,
                         cudaFuncAttributeMaxDynamicSharedMemorySize, GEMM_SMEM);
    cudaFuncSetAttribute(flash_mma_kernel,
                         cudaFuncAttributeMaxDynamicSharedMemorySize, FLASH_SMEM);

    // 0) conversions
    convert_half_kernel<<<2048, 256>>>(x, x16, MTOT * DMODEL / 4);
    transpose_half_kernel<<<dim3(N_QKV / 32, DMODEL / 32), dim3(32, 8)>>>(
        w_qkv, wq, DMODEL, N_QKV);
    transpose_half_kernel<<<dim3(DMODEL / 32, DMODEL / 32), dim3(32, 8)>>>(
        w_out, wo, DMODEL, DMODEL);

    // 1) QKV projection -> q/k/v head-major fp16 (q unscaled)
    {
        dim3 grid(N_QKV / 128, MTOT / 128);
        gemm_mma_kernel<true><<<grid, 256, GEMM_SMEM>>>(
            x16, wq, b_qkv, nullptr, q16, k16, v16, MTOT, N_QKV, DMODEL);
    }
    // 2) Tensor-core flash attention -> ctx fp16
    {
        dim3 grid(SEQ / 128, NHEAD, BATCH);
        flash_mma_kernel<<<grid, 256, FLASH_SMEM>>>(q16, k16, v16, ctx);
    }
    // 3) Output projection -> fp32 out
    {
        dim3 grid(DMODEL / 128, MTOT / 128);
        gemm_mma_kernel<false><<<grid, 256, GEMM_SMEM>>>(
            ctx, wo, b_out, out, nullptr, nullptr, nullptr, MTOT, DMODEL, DMODEL);
    }
}